// round 1
// baseline (speedup 1.0000x reference)
#include <cuda_runtime.h>
#include <math.h>

#define BATCH 4
#define SEQ   2048
#define DIM   1024
#define HEADS 16
#define DHEAD 64
#define INNER 1024
#define QKV3  3072
#define SCALE 0.125f
#define NEGV  (-1e9f)

// Scratch (device globals: allocation-free, graph-capturable)
__device__ float g_qkv[(size_t)BATCH * SEQ * QKV3];   // 96 MB
__device__ float g_attn[(size_t)BATCH * SEQ * INNER]; // 32 MB

// ---------------------------------------------------------------------------
// Classic 128x128x8 SGEMM, 256 threads, 8x8 per thread, float4 loads.
// Shapes here are always multiples of tile sizes -> no bounds checks.
// ---------------------------------------------------------------------------
__global__ __launch_bounds__(256)
void sgemm128(const float* __restrict__ A, const float* __restrict__ B,
              float* __restrict__ C, int M, int Nn, int K,
              const float* __restrict__ bias)
{
    __shared__ float As[8][128];
    __shared__ float Bs[8][128];
    const int tid  = threadIdx.x;
    const int brow = blockIdx.y * 128;
    const int bcol = blockIdx.x * 128;
    const int tx = tid & 15;
    const int ty = tid >> 4;

    float acc[8][8];
#pragma unroll
    for (int i = 0; i < 8; i++)
#pragma unroll
        for (int j = 0; j < 8; j++) acc[i][j] = 0.f;

    const int arow = tid >> 1, acol = (tid & 1) * 4;     // A: 128 rows x 8 cols
    const int brB  = tid >> 5, bcB  = (tid & 31) * 4;    // B: 8 rows x 128 cols

    for (int kt = 0; kt < K; kt += 8) {
        float4 av = *(const float4*)&A[(size_t)(brow + arow) * K + kt + acol];
        float4 bv = *(const float4*)&B[(size_t)(kt + brB) * Nn + bcol + bcB];
        __syncthreads();  // protect previous iteration's reads
        As[acol + 0][arow] = av.x;
        As[acol + 1][arow] = av.y;
        As[acol + 2][arow] = av.z;
        As[acol + 3][arow] = av.w;
        *(float4*)&Bs[brB][bcB] = bv;
        __syncthreads();
#pragma unroll
        for (int k = 0; k < 8; k++) {
            float ra[8], rb[8];
#pragma unroll
            for (int i = 0; i < 8; i++) ra[i] = As[k][ty * 8 + i];
#pragma unroll
            for (int j = 0; j < 8; j++) rb[j] = Bs[k][tx * 8 + j];
#pragma unroll
            for (int i = 0; i < 8; i++)
#pragma unroll
                for (int j = 0; j < 8; j++) acc[i][j] += ra[i] * rb[j];
        }
    }

#pragma unroll
    for (int i = 0; i < 8; i++) {
        const int row = brow + ty * 8 + i;
#pragma unroll
        for (int j = 0; j < 8; j += 4) {
            const int col = bcol + tx * 8 + j;
            float4 v = make_float4(acc[i][j], acc[i][j + 1], acc[i][j + 2], acc[i][j + 3]);
            if (bias) {
                v.x += bias[col];  v.y += bias[col + 1];
                v.z += bias[col + 2]; v.w += bias[col + 3];
            }
            *(float4*)&C[(size_t)row * Nn + col] = v;
        }
    }
}

// ---------------------------------------------------------------------------
// Flash attention, fp32, causal. Grid: (B*HEADS, SEQ/64). 256 threads.
// 64-query tile; each thread owns one query row quarter (16 output dims).
// smem: Q(16K) + shared K/V buffer(16K) + P(16K) = 48 KB.
// ---------------------------------------------------------------------------
__global__ __launch_bounds__(256)
void flash_attn()
{
    __shared__ float sQ[64][64];
    __shared__ float sKV[64][64];
    __shared__ float sP[64][64];

    const int bh = blockIdx.x;
    const int b  = bh / HEADS, h = bh % HEADS;
    const int qb = blockIdx.y;
    const int tid = threadIdx.x;

    const float* base = g_qkv + (size_t)b * SEQ * QKV3;
    const float* Qp = base + h * DHEAD;
    const float* Kp = base + INNER + h * DHEAD;
    const float* Vp = base + 2 * INNER + h * DHEAD;

    // Load Q tile (pre-scaled)
    for (int idx = tid; idx < 64 * 64; idx += 256) {
        const int r = idx >> 6, d = idx & 63;
        sQ[r][d] = Qp[(size_t)(qb * 64 + r) * QKV3 + d] * SCALE;
    }

    const int row = tid >> 2;        // 0..63
    const int quad = tid & 3;        // 0..3  (16 key cols / 16 out dims each)
    const int gi = qb * 64 + row;

    float m = -1e30f, l = 0.f;
    float o[16];
#pragma unroll
    for (int i = 0; i < 16; i++) o[i] = 0.f;

    for (int kb = 0; kb <= qb; kb++) {
        __syncthreads();
        // K tile -> sKV
        for (int idx = tid; idx < 64 * 64; idx += 256) {
            const int r = idx >> 6, d = idx & 63;
            sKV[r][d] = Kp[(size_t)(kb * 64 + r) * QKV3 + d];
        }
        __syncthreads();

        // S = Q K^T (16 cols per thread)
        float s[16];
#pragma unroll
        for (int jj = 0; jj < 16; jj++) {
            const int j = quad * 16 + jj;
            const float4* qr = (const float4*)sQ[row];
            const float4* kr = (const float4*)sKV[j];
            float a0 = 0.f, a1 = 0.f, a2 = 0.f, a3 = 0.f;
#pragma unroll
            for (int d4 = 0; d4 < 16; d4++) {
                float4 qa = qr[d4], ka = kr[d4];
                a0 += qa.x * ka.x; a1 += qa.y * ka.y;
                a2 += qa.z * ka.z; a3 += qa.w * ka.w;
            }
            const float acc = (a0 + a1) + (a2 + a3);
            const int gj = kb * 64 + j;
            s[jj] = (gj <= gi) ? acc : NEGV;
        }

        // Row max across the 4 quads (lanes differ by 1,2)
        float mx = s[0];
#pragma unroll
        for (int jj = 1; jj < 16; jj++) mx = fmaxf(mx, s[jj]);
        mx = fmaxf(mx, __shfl_xor_sync(0xffffffffu, mx, 1));
        mx = fmaxf(mx, __shfl_xor_sync(0xffffffffu, mx, 2));
        const float m_new = fmaxf(m, mx);
        const float corr = __expf(m - m_new);

        float ps = 0.f;
#pragma unroll
        for (int jj = 0; jj < 16; jj++) {
            const float p = __expf(s[jj] - m_new);
            s[jj] = p;
            ps += p;
        }
        ps += __shfl_xor_sync(0xffffffffu, ps, 1);
        ps += __shfl_xor_sync(0xffffffffu, ps, 2);
        l = l * corr + ps;
        m = m_new;
#pragma unroll
        for (int i = 0; i < 16; i++) o[i] *= corr;
#pragma unroll
        for (int jj = 0; jj < 16; jj++) sP[row][quad * 16 + jj] = s[jj];
        __syncthreads();

        // V tile -> sKV (reuse)
        for (int idx = tid; idx < 64 * 64; idx += 256) {
            const int r = idx >> 6, d = idx & 63;
            sKV[r][d] = Vp[(size_t)(kb * 64 + r) * QKV3 + d];
        }
        __syncthreads();

        // O += P V (16 dims per thread)
#pragma unroll 4
        for (int j = 0; j < 64; j++) {
            const float p = sP[row][j];
            const float* vr = &sKV[j][quad * 16];
#pragma unroll
            for (int i = 0; i < 16; i++) o[i] += p * vr[i];
        }
    }

    const float inv = 1.f / l;
    float* op = g_attn + (size_t)(b * SEQ + gi) * INNER + h * DHEAD + quad * 16;
#pragma unroll
    for (int i = 0; i < 16; i++) op[i] = o[i] * inv;
}

// ---------------------------------------------------------------------------
extern "C" void kernel_launch(void* const* d_in, const int* in_sizes, int n_in,
                              void* d_out, int out_size)
{
    const float* x     = (const float*)d_in[0];
    const float* w_qkv = (const float*)d_in[1];
    const float* w_out = (const float*)d_in[2];
    const float* b_out = (const float*)d_in[3];
    float* out = (float*)d_out;

    float *qkv, *attn;
    cudaGetSymbolAddress((void**)&qkv, g_qkv);
    cudaGetSymbolAddress((void**)&attn, g_attn);

    const int M = BATCH * SEQ;  // 8192

    // 1) QKV projection: [8192,1024] x [1024,3072]
    sgemm128<<<dim3(QKV3 / 128, M / 128), 256>>>(x, w_qkv, qkv, M, QKV3, DIM, nullptr);

    // 2) Causal flash attention -> g_attn [8192, 1024]
    flash_attn<<<dim3(BATCH * HEADS, SEQ / 64), 256>>>();

    // 3) Output projection + bias: [8192,1024] x [1024,1024]
    sgemm128<<<dim3(DIM / 128, M / 128), 256>>>(attn, w_out, out, M, DIM, INNER, b_out);
}

// round 3
// speedup vs baseline: 4.1176x; 4.1176x over previous
#include <cuda_runtime.h>
#include <cuda_bf16.h>
#include <cstdint>
#include <math.h>

#define BATCH 4
#define SEQ   2048
#define DIM   1024
#define HEADS 16
#define DHEAD 64
#define INNER 1024
#define QKV3  3072
#define SCALE 0.125f
#define NEGV  (-1e9f)
#define MTOT  (BATCH * SEQ)   // 8192

// ---------------------------------------------------------------------------
// Device scratch (allocation-free)
// ---------------------------------------------------------------------------
__device__ float          g_qkv[(size_t)MTOT * QKV3];        // 96 MB f32
__device__ __nv_bfloat16  g_xhi[(size_t)MTOT * DIM];
__device__ __nv_bfloat16  g_xlo[(size_t)MTOT * DIM];
__device__ __nv_bfloat16  g_wqkv_hi[(size_t)QKV3 * DIM];     // [N][K]
__device__ __nv_bfloat16  g_wqkv_lo[(size_t)QKV3 * DIM];
__device__ __nv_bfloat16  g_wout_hi[(size_t)DIM * INNER];    // [N][K]
__device__ __nv_bfloat16  g_wout_lo[(size_t)DIM * INNER];
__device__ __nv_bfloat16  g_attnhi[(size_t)MTOT * INNER];
__device__ __nv_bfloat16  g_attnlo[(size_t)MTOT * INNER];

// ---------------------------------------------------------------------------
__device__ __forceinline__ uint32_t smem_to_u32(const void* p) {
    uint32_t a;
    asm("{ .reg .u64 t; cvta.to.shared.u64 t, %1; cvt.u32.u64 %0, t; }" : "=r"(a) : "l"(p));
    return a;
}
__device__ __forceinline__ void ldsm4(uint32_t (&r)[4], uint32_t addr) {
    asm volatile("ldmatrix.sync.aligned.m8n8.x4.shared.b16 {%0,%1,%2,%3}, [%4];"
        : "=r"(r[0]), "=r"(r[1]), "=r"(r[2]), "=r"(r[3]) : "r"(addr));
}
__device__ __forceinline__ void mma16816(float (&d)[4], const uint32_t (&a)[4],
                                         uint32_t b0, uint32_t b1) {
    asm volatile("mma.sync.aligned.m16n8k16.row.col.f32.bf16.bf16.f32 "
        "{%0,%1,%2,%3}, {%4,%5,%6,%7}, {%8,%9}, {%0,%1,%2,%3};"
        : "+f"(d[0]), "+f"(d[1]), "+f"(d[2]), "+f"(d[3])
        : "r"(a[0]), "r"(a[1]), "r"(a[2]), "r"(a[3]), "r"(b0), "r"(b1));
}
__device__ __forceinline__ void split2(float v, __nv_bfloat16& hi, __nv_bfloat16& lo) {
    hi = __float2bfloat16(v);
    lo = __float2bfloat16(v - __bfloat162float(hi));
}

// ---------------------------------------------------------------------------
// Conversion kernels
// ---------------------------------------------------------------------------
__global__ __launch_bounds__(256)
void split_rows(const float* __restrict__ in, __nv_bfloat16* __restrict__ hi,
                __nv_bfloat16* __restrict__ lo, int n4)
{
    int i = blockIdx.x * 256 + threadIdx.x;
    if (i >= n4) return;
    float4 v = ((const float4*)in)[i];
    __nv_bfloat16 h[4], l[4];
    split2(v.x, h[0], l[0]); split2(v.y, h[1], l[1]);
    split2(v.z, h[2], l[2]); split2(v.w, h[3], l[3]);
    uint2 hv, lv;
    hv.x = ((uint32_t)__bfloat16_as_ushort(h[1]) << 16) | __bfloat16_as_ushort(h[0]);
    hv.y = ((uint32_t)__bfloat16_as_ushort(h[3]) << 16) | __bfloat16_as_ushort(h[2]);
    lv.x = ((uint32_t)__bfloat16_as_ushort(l[1]) << 16) | __bfloat16_as_ushort(l[0]);
    lv.y = ((uint32_t)__bfloat16_as_ushort(l[3]) << 16) | __bfloat16_as_ushort(l[2]);
    ((uint2*)hi)[i] = hv;
    ((uint2*)lo)[i] = lv;
}

// in[K][N] -> out[N][K] (hi/lo)
__global__ __launch_bounds__(256)
void split_T(const float* __restrict__ in, __nv_bfloat16* __restrict__ hi,
             __nv_bfloat16* __restrict__ lo, int K, int N)
{
    __shared__ float t[32][33];
    const int k0 = blockIdx.y * 32, n0 = blockIdx.x * 32;
    const int tx = threadIdx.x & 31, ty = threadIdx.x >> 5;
#pragma unroll
    for (int i = 0; i < 32; i += 8)
        t[ty + i][tx] = in[(size_t)(k0 + ty + i) * N + n0 + tx];
    __syncthreads();
#pragma unroll
    for (int i = 0; i < 32; i += 8) {
        __nv_bfloat16 h, l;
        split2(t[tx][ty + i], h, l);
        size_t o = (size_t)(n0 + ty + i) * K + k0 + tx;
        hi[o] = h; lo[o] = l;
    }
}

// ---------------------------------------------------------------------------
// mma.sync bf16-split GEMM: C[M,N] = A[M,K] * B[N,K]^T (+bias)
// 128x128 block, BK=32, 8 warps (2m x 4n), warp tile 64x32.
// smem rows padded to 40 halves (80B) -> conflict-free ldmatrix.
// dyn smem = 2 * 4 * 128*80 = 81920 B
// ---------------------------------------------------------------------------
#define SROWB 80                  // bytes per smem row
#define MATB  (128 * SROWB)       // 10240 per matrix tile
#define BUFB  (4 * MATB)          // 40960 per buffer

__global__ __launch_bounds__(256)
void gemm_mma(const __nv_bfloat16* __restrict__ Ahi, const __nv_bfloat16* __restrict__ Alo,
              const __nv_bfloat16* __restrict__ Bhi, const __nv_bfloat16* __restrict__ Blo,
              float* __restrict__ C, int Nout, int K, const float* __restrict__ bias)
{
    extern __shared__ char sm[];
    const uint32_t sb = smem_to_u32(sm);
    const int tid = threadIdx.x;
    const int wid = tid >> 5, lane = tid & 31;
    const int wm = wid >> 2, wn = wid & 3;
    const int brow = blockIdx.y * 128, bcol = blockIdx.x * 128;

    const __nv_bfloat16* gsrc[4] = {
        Ahi + (size_t)brow * K, Alo + (size_t)brow * K,
        Bhi + (size_t)bcol * K, Blo + (size_t)bcol * K };

    const int r0 = tid >> 2;            // 0..63 (rows r0 and r0+64)
    const int kh = (tid & 3) * 8;       // half offset within 32-wide chunk

    float acc[4][4][4];
#pragma unroll
    for (int mt = 0; mt < 4; mt++)
#pragma unroll
        for (int nt = 0; nt < 4; nt++)
#pragma unroll
            for (int i = 0; i < 4; i++) acc[mt][nt][i] = 0.f;

    uint4 pre[4][2];

    // prologue: chunk 0 -> buf 0
#pragma unroll
    for (int m = 0; m < 4; m++)
#pragma unroll
        for (int s = 0; s < 2; s++)
            pre[m][s] = *(const uint4*)(gsrc[m] + (size_t)(r0 + s * 64) * K + kh);
#pragma unroll
    for (int m = 0; m < 4; m++)
#pragma unroll
        for (int s = 0; s < 2; s++)
            *(uint4*)(sm + m * MATB + (r0 + s * 64) * SROWB + kh * 2) = pre[m][s];
    __syncthreads();

    const int nch = K / 32;
    const uint32_t arow = (uint32_t)(wm * 64 + (lane & 15)) * SROWB + (lane >> 4) * 16;
    const uint32_t brow_s = (uint32_t)(wn * 32 + (lane & 15)) * SROWB + (lane >> 4) * 16;

    for (int c = 0; c < nch; c++) {
        if (c + 1 < nch) {
            const int koff = (c + 1) * 32 + kh;
#pragma unroll
            for (int m = 0; m < 4; m++)
#pragma unroll
                for (int s = 0; s < 2; s++)
                    pre[m][s] = *(const uint4*)(gsrc[m] + (size_t)(r0 + s * 64) * K + koff);
        }
        const uint32_t base = sb + (c & 1) * BUFB;
#pragma unroll
        for (int ks = 0; ks < 2; ks++) {
            const uint32_t kso = ks * 32;
            uint32_t afh[4][4], afl[4][4];
#pragma unroll
            for (int mt = 0; mt < 4; mt++) {
                ldsm4(afh[mt], base + 0 * MATB + arow + mt * 16 * SROWB + kso);
                ldsm4(afl[mt], base + 1 * MATB + arow + mt * 16 * SROWB + kso);
            }
            uint32_t bfh[4][2], bfl[4][2];
#pragma unroll
            for (int nb = 0; nb < 2; nb++) {
                uint32_t t[4];
                ldsm4(t, base + 2 * MATB + brow_s + nb * 16 * SROWB + kso);
                bfh[nb * 2 + 0][0] = t[0]; bfh[nb * 2 + 0][1] = t[2];
                bfh[nb * 2 + 1][0] = t[1]; bfh[nb * 2 + 1][1] = t[3];
                ldsm4(t, base + 3 * MATB + brow_s + nb * 16 * SROWB + kso);
                bfl[nb * 2 + 0][0] = t[0]; bfl[nb * 2 + 0][1] = t[2];
                bfl[nb * 2 + 1][0] = t[1]; bfl[nb * 2 + 1][1] = t[3];
            }
#pragma unroll
            for (int mt = 0; mt < 4; mt++)
#pragma unroll
                for (int nt = 0; nt < 4; nt++) {
                    mma16816(acc[mt][nt], afh[mt], bfh[nt][0], bfh[nt][1]);
                    mma16816(acc[mt][nt], afh[mt], bfl[nt][0], bfl[nt][1]);
                    mma16816(acc[mt][nt], afl[mt], bfh[nt][0], bfh[nt][1]);
                }
        }
        if (c + 1 < nch) {
            char* d = sm + ((c + 1) & 1) * BUFB;
#pragma unroll
            for (int m = 0; m < 4; m++)
#pragma unroll
                for (int s = 0; s < 2; s++)
                    *(uint4*)(d + m * MATB + (r0 + s * 64) * SROWB + kh * 2) = pre[m][s];
        }
        __syncthreads();
    }

    // Epilogue
    const int tg = lane >> 2, tq = lane & 3;
#pragma unroll
    for (int mt = 0; mt < 4; mt++) {
        const int row = brow + wm * 64 + mt * 16 + tg;
#pragma unroll
        for (int nt = 0; nt < 4; nt++) {
            const int col = bcol + wn * 32 + nt * 8 + tq * 2;
            float b0 = 0.f, b1 = 0.f;
            if (bias) { b0 = bias[col]; b1 = bias[col + 1]; }
            *(float2*)&C[(size_t)row * Nout + col] =
                make_float2(acc[mt][nt][0] + b0, acc[mt][nt][1] + b1);
            *(float2*)&C[(size_t)(row + 8) * Nout + col] =
                make_float2(acc[mt][nt][2] + b0, acc[mt][nt][3] + b1);
        }
    }
}

// ---------------------------------------------------------------------------
// Register-blocked causal flash attention (fp32), bf16 hi/lo output.
// grid (B*HEADS, SEQ/64), 256 threads, 4x4 microkernels.
// dyn smem: Qt[64][68] + Kt[64][68] + P[64][68] + V[64][64] = 68608 B
// ---------------------------------------------------------------------------
__global__ __launch_bounds__(256)
void flash_attn2(__nv_bfloat16* __restrict__ ohi, __nv_bfloat16* __restrict__ olo)
{
    extern __shared__ float smf[];
    float* sQt = smf;
    float* sKt = smf + 64 * 68;
    float* sP  = smf + 2 * 64 * 68;
    float* sV  = smf + 3 * 64 * 68;

    const int bh = blockIdx.x;
    const int b = bh / HEADS, h = bh % HEADS;
    const int qb = blockIdx.y;
    const int tid = threadIdx.x;
    const int tr = tid >> 4, tc = tid & 15;
    const int i0 = tr * 4, j0 = tc * 4, d0 = tc * 4;

    const float* base = g_qkv + (size_t)b * SEQ * QKV3;
    const float* Qp = base + h * DHEAD;
    const float* Kp = base + INNER + h * DHEAD;
    const float* Vp = base + 2 * INNER + h * DHEAD;

    for (int idx = tid; idx < 1024; idx += 256) {
        const int r = idx >> 4, c4 = (idx & 15) * 4;
        float4 v = *(const float4*)(Qp + (size_t)(qb * 64 + r) * QKV3 + c4);
        sQt[(c4 + 0) * 68 + r] = v.x * SCALE;
        sQt[(c4 + 1) * 68 + r] = v.y * SCALE;
        sQt[(c4 + 2) * 68 + r] = v.z * SCALE;
        sQt[(c4 + 3) * 68 + r] = v.w * SCALE;
    }

    float m[4], l[4], o[4][4];
#pragma unroll
    for (int i = 0; i < 4; i++) {
        m[i] = -1e30f; l[i] = 0.f;
#pragma unroll
        for (int j = 0; j < 4; j++) o[i][j] = 0.f;
    }

    for (int kb = 0; kb <= qb; kb++) {
        __syncthreads();
        for (int idx = tid; idx < 1024; idx += 256) {
            const int r = idx >> 4, c4 = (idx & 15) * 4;
            float4 kv = *(const float4*)(Kp + (size_t)(kb * 64 + r) * QKV3 + c4);
            sKt[(c4 + 0) * 68 + r] = kv.x;
            sKt[(c4 + 1) * 68 + r] = kv.y;
            sKt[(c4 + 2) * 68 + r] = kv.z;
            sKt[(c4 + 3) * 68 + r] = kv.w;
            float4 vv = *(const float4*)(Vp + (size_t)(kb * 64 + r) * QKV3 + c4);
            *(float4*)(sV + r * 64 + c4) = vv;
        }
        __syncthreads();

        float s[4][4];
#pragma unroll
        for (int i = 0; i < 4; i++)
#pragma unroll
            for (int j = 0; j < 4; j++) s[i][j] = 0.f;
#pragma unroll 4
        for (int d = 0; d < 64; d++) {
            float4 qa = *(const float4*)(sQt + d * 68 + i0);
            float4 ka = *(const float4*)(sKt + d * 68 + j0);
            float q[4] = {qa.x, qa.y, qa.z, qa.w};
            float k[4] = {ka.x, ka.y, ka.z, ka.w};
#pragma unroll
            for (int i = 0; i < 4; i++)
#pragma unroll
                for (int j = 0; j < 4; j++) s[i][j] += q[i] * k[j];
        }
        if (kb == qb) {
#pragma unroll
            for (int i = 0; i < 4; i++)
#pragma unroll
                for (int j = 0; j < 4; j++)
                    if (j0 + j > i0 + i) s[i][j] = NEGV;
        }

#pragma unroll
        for (int i = 0; i < 4; i++) {
            float mx = fmaxf(fmaxf(s[i][0], s[i][1]), fmaxf(s[i][2], s[i][3]));
            mx = fmaxf(mx, __shfl_xor_sync(0xffffffffu, mx, 1));
            mx = fmaxf(mx, __shfl_xor_sync(0xffffffffu, mx, 2));
            mx = fmaxf(mx, __shfl_xor_sync(0xffffffffu, mx, 4));
            mx = fmaxf(mx, __shfl_xor_sync(0xffffffffu, mx, 8));
            const float mn = fmaxf(m[i], mx);
            const float corr = __expf(m[i] - mn);
            float ps = 0.f;
#pragma unroll
            for (int j = 0; j < 4; j++) {
                const float p = __expf(s[i][j] - mn);
                s[i][j] = p; ps += p;
            }
            ps += __shfl_xor_sync(0xffffffffu, ps, 1);
            ps += __shfl_xor_sync(0xffffffffu, ps, 2);
            ps += __shfl_xor_sync(0xffffffffu, ps, 4);
            ps += __shfl_xor_sync(0xffffffffu, ps, 8);
            l[i] = l[i] * corr + ps;
            m[i] = mn;
#pragma unroll
            for (int j = 0; j < 4; j++) o[i][j] *= corr;
            *(float4*)(sP + (i0 + i) * 68 + j0) = make_float4(s[i][0], s[i][1], s[i][2], s[i][3]);
        }
        __syncthreads();

#pragma unroll 4
        for (int j = 0; j < 64; j++) {
            float4 va = *(const float4*)(sV + j * 64 + d0);
            float v[4] = {va.x, va.y, va.z, va.w};
#pragma unroll
            for (int i = 0; i < 4; i++) {
                const float p = sP[(i0 + i) * 68 + j];
#pragma unroll
                for (int dd = 0; dd < 4; dd++) o[i][dd] += p * v[dd];
            }
        }
    }

#pragma unroll
    for (int i = 0; i < 4; i++) {
        const float inv = 1.f / l[i];
        const size_t ob = (size_t)(b * SEQ + qb * 64 + i0 + i) * INNER + h * DHEAD + d0;
#pragma unroll
        for (int dd = 0; dd < 4; dd++) {
            __nv_bfloat16 hh, ll;
            split2(o[i][dd] * inv, hh, ll);
            ohi[ob + dd] = hh;
            olo[ob + dd] = ll;
        }
    }
}

// ---------------------------------------------------------------------------
extern "C" void kernel_launch(void* const* d_in, const int* in_sizes, int n_in,
                              void* d_out, int out_size)
{
    const float* x     = (const float*)d_in[0];
    const float* w_qkv = (const float*)d_in[1];
    const float* w_out = (const float*)d_in[2];
    const float* b_out = (const float*)d_in[3];
    float* out = (float*)d_out;

    float *qkv;
    __nv_bfloat16 *xhi, *xlo, *wqh, *wql, *woh, *wol, *ahi, *alo;
    cudaGetSymbolAddress((void**)&qkv, g_qkv);
    cudaGetSymbolAddress((void**)&xhi, g_xhi);
    cudaGetSymbolAddress((void**)&xlo, g_xlo);
    cudaGetSymbolAddress((void**)&wqh, g_wqkv_hi);
    cudaGetSymbolAddress((void**)&wql, g_wqkv_lo);
    cudaGetSymbolAddress((void**)&woh, g_wout_hi);
    cudaGetSymbolAddress((void**)&wol, g_wout_lo);
    cudaGetSymbolAddress((void**)&ahi, g_attnhi);
    cudaGetSymbolAddress((void**)&alo, g_attnlo);

    cudaFuncSetAttribute(gemm_mma, cudaFuncAttributeMaxDynamicSharedMemorySize, 2 * BUFB);
    cudaFuncSetAttribute(flash_attn2, cudaFuncAttributeMaxDynamicSharedMemorySize, 68608);

    // 1) Splits
    {
        int n4 = MTOT * DIM / 4;
        split_rows<<<(n4 + 255) / 256, 256>>>(x, xhi, xlo, n4);
        split_T<<<dim3(QKV3 / 32, DIM / 32), 256>>>(w_qkv, wqh, wql, DIM, QKV3);
        split_T<<<dim3(DIM / 32, INNER / 32), 256>>>(w_out, woh, wol, INNER, DIM);
    }
    // 2) QKV projection
    gemm_mma<<<dim3(QKV3 / 128, MTOT / 128), 256, 2 * BUFB>>>(
        xhi, xlo, wqh, wql, qkv, QKV3, DIM, nullptr);
    // 3) Attention
    flash_attn2<<<dim3(BATCH * HEADS, SEQ / 64), 256, 68608>>>(ahi, alo);
    // 4) Output projection + bias
    gemm_mma<<<dim3(DIM / 128, MTOT / 128), 256, 2 * BUFB>>>(
        ahi, alo, woh, wol, out, DIM, INNER, b_out);
}

// round 5
// speedup vs baseline: 5.8789x; 1.4277x over previous
#include <cuda_runtime.h>
#include <cuda_bf16.h>
#include <cstdint>
#include <math.h>

#define BATCH 4
#define SEQ   2048
#define DIM   1024
#define HEADS 16
#define DHEAD 64
#define INNER 1024
#define QKV3  3072
#define SCALE 0.125f
#define NEGV  (-1e9f)
#define MTOT  (BATCH * SEQ)   // 8192

// ---------------------------------------------------------------------------
// Device scratch (allocation-free)
// ---------------------------------------------------------------------------
__device__ float          g_qkv[(size_t)MTOT * QKV3];        // 96 MB f32
__device__ __nv_bfloat16  g_xhi[(size_t)MTOT * DIM];
__device__ __nv_bfloat16  g_xlo[(size_t)MTOT * DIM];
__device__ __nv_bfloat16  g_wqkv_hi[(size_t)QKV3 * DIM];     // [N][K]
__device__ __nv_bfloat16  g_wqkv_lo[(size_t)QKV3 * DIM];
__device__ __nv_bfloat16  g_wout_hi[(size_t)DIM * INNER];    // [N][K]
__device__ __nv_bfloat16  g_wout_lo[(size_t)DIM * INNER];
__device__ __nv_bfloat16  g_attnhi[(size_t)MTOT * INNER];
__device__ __nv_bfloat16  g_attnlo[(size_t)MTOT * INNER];

// ---------------------------------------------------------------------------
__device__ __forceinline__ uint32_t smem_to_u32(const void* p) {
    uint32_t a;
    asm("{ .reg .u64 t; cvta.to.shared.u64 t, %1; cvt.u32.u64 %0, t; }" : "=r"(a) : "l"(p));
    return a;
}
__device__ __forceinline__ void ldsm4(uint32_t (&r)[4], uint32_t addr) {
    asm volatile("ldmatrix.sync.aligned.m8n8.x4.shared.b16 {%0,%1,%2,%3}, [%4];"
        : "=r"(r[0]), "=r"(r[1]), "=r"(r[2]), "=r"(r[3]) : "r"(addr));
}
__device__ __forceinline__ void mma16816(float (&d)[4], const uint32_t (&a)[4],
                                         uint32_t b0, uint32_t b1) {
    asm volatile("mma.sync.aligned.m16n8k16.row.col.f32.bf16.bf16.f32 "
        "{%0,%1,%2,%3}, {%4,%5,%6,%7}, {%8,%9}, {%0,%1,%2,%3};"
        : "+f"(d[0]), "+f"(d[1]), "+f"(d[2]), "+f"(d[3])
        : "r"(a[0]), "r"(a[1]), "r"(a[2]), "r"(a[3]), "r"(b0), "r"(b1));
}
__device__ __forceinline__ void cpasync16(uint32_t dst, const void* src) {
    asm volatile("cp.async.cg.shared.global [%0], [%1], 16;" :: "r"(dst), "l"(src));
}
#define CP_COMMIT  asm volatile("cp.async.commit_group;" ::: "memory")
#define CP_WAIT2   asm volatile("cp.async.wait_group 2;" ::: "memory")
#define CP_WAIT0   asm volatile("cp.async.wait_group 0;" ::: "memory")

__device__ __forceinline__ void split2(float v, __nv_bfloat16& hi, __nv_bfloat16& lo) {
    hi = __float2bfloat16(v);
    lo = __float2bfloat16(v - __bfloat162float(hi));
}
__device__ __forceinline__ uint32_t packbf(__nv_bfloat16 a, __nv_bfloat16 b) {
    return (uint32_t)__bfloat16_as_ushort(a) | ((uint32_t)__bfloat16_as_ushort(b) << 16);
}
// split a pair of floats into packed hi/lo bf16x2
__device__ __forceinline__ void packsplit2(float a, float b, uint32_t& hi, uint32_t& lo) {
    __nv_bfloat16 ah, al, bh, bl;
    split2(a, ah, al); split2(b, bh, bl);
    hi = packbf(ah, bh); lo = packbf(al, bl);
}

// ---------------------------------------------------------------------------
// Conversion kernels
// ---------------------------------------------------------------------------
__global__ __launch_bounds__(256)
void split_rows(const float* __restrict__ in, __nv_bfloat16* __restrict__ hi,
                __nv_bfloat16* __restrict__ lo, int n4)
{
    int i = blockIdx.x * 256 + threadIdx.x;
    if (i >= n4) return;
    float4 v = ((const float4*)in)[i];
    __nv_bfloat16 h[4], l[4];
    split2(v.x, h[0], l[0]); split2(v.y, h[1], l[1]);
    split2(v.z, h[2], l[2]); split2(v.w, h[3], l[3]);
    uint2 hv, lv;
    hv.x = packbf(h[0], h[1]); hv.y = packbf(h[2], h[3]);
    lv.x = packbf(l[0], l[1]); lv.y = packbf(l[2], l[3]);
    ((uint2*)hi)[i] = hv;
    ((uint2*)lo)[i] = lv;
}

// in[K][N] -> out[N][K] (hi/lo)
__global__ __launch_bounds__(256)
void split_T(const float* __restrict__ in, __nv_bfloat16* __restrict__ hi,
             __nv_bfloat16* __restrict__ lo, int K, int N)
{
    __shared__ float t[32][33];
    const int k0 = blockIdx.y * 32, n0 = blockIdx.x * 32;
    const int tx = threadIdx.x & 31, ty = threadIdx.x >> 5;
#pragma unroll
    for (int i = 0; i < 32; i += 8)
        t[ty + i][tx] = in[(size_t)(k0 + ty + i) * N + n0 + tx];
    __syncthreads();
#pragma unroll
    for (int i = 0; i < 32; i += 8) {
        __nv_bfloat16 h, l;
        split2(t[tx][ty + i], h, l);
        size_t o = (size_t)(n0 + ty + i) * K + k0 + tx;
        hi[o] = h; lo[o] = l;
    }
}

// ---------------------------------------------------------------------------
// mma.sync bf16-split GEMM: C[M,N] = A[M,K]*B[N,K]^T (+bias)
// 128x128 block, BK=32, 8 warps (2m x 4n), 3-stage cp.async pipeline.
// dyn smem = 3 * 40960 = 122880 B
// ---------------------------------------------------------------------------
#define SROWB 80
#define MATB  (128 * SROWB)       // 10240
#define BUFB  (4 * MATB)          // 40960

__global__ __launch_bounds__(256)
void gemm_mma(const __nv_bfloat16* __restrict__ Ahi, const __nv_bfloat16* __restrict__ Alo,
              const __nv_bfloat16* __restrict__ Bhi, const __nv_bfloat16* __restrict__ Blo,
              float* __restrict__ C, int Nout, int K, const float* __restrict__ bias)
{
    extern __shared__ char sm[];
    const uint32_t sb = smem_to_u32(sm);
    const int tid = threadIdx.x;
    const int wid = tid >> 5, lane = tid & 31;
    const int wm = wid >> 2, wn = wid & 3;
    const int brow = blockIdx.y * 128, bcol = blockIdx.x * 128;

    const __nv_bfloat16* gsrc[4] = {
        Ahi + (size_t)brow * K, Alo + (size_t)brow * K,
        Bhi + (size_t)bcol * K, Blo + (size_t)bcol * K };

    const int r0 = tid >> 2;
    const int kh = (tid & 3) * 8;    // half offset inside 32-wide chunk
    const int nch = K / 32;

    float acc[4][4][4];
#pragma unroll
    for (int mt = 0; mt < 4; mt++)
#pragma unroll
        for (int nt = 0; nt < 4; nt++)
#pragma unroll
            for (int i = 0; i < 4; i++) acc[mt][nt][i] = 0.f;

    // async-copy issue for chunk c into buffer c%3
    auto issue = [&](int c) {
        const uint32_t d = sb + (uint32_t)(c % 3) * BUFB;
        const int koff = c * 32 + kh;
#pragma unroll
        for (int m = 0; m < 4; m++)
#pragma unroll
            for (int s = 0; s < 2; s++)
                cpasync16(d + m * MATB + (r0 + s * 64) * SROWB + kh * 2,
                          gsrc[m] + (size_t)(r0 + s * 64) * K + koff);
    };

    issue(0); CP_COMMIT;
    issue(1); CP_COMMIT;

    const uint32_t arow  = (uint32_t)(wm * 64 + (lane & 15)) * SROWB + (lane >> 4) * 16;
    const uint32_t brow_s = (uint32_t)(wn * 32 + (lane & 15)) * SROWB + (lane >> 4) * 16;

    for (int c = 0; c < nch; c++) {
        if (c + 2 < nch) { issue(c + 2); CP_COMMIT; CP_WAIT2; }
        else             { CP_WAIT0; }
        __syncthreads();
        const uint32_t base = sb + (uint32_t)(c % 3) * BUFB;
#pragma unroll
        for (int ks = 0; ks < 2; ks++) {
            const uint32_t kso = ks * 32;
            uint32_t afh[4][4], afl[4][4];
#pragma unroll
            for (int mt = 0; mt < 4; mt++) {
                ldsm4(afh[mt], base + 0 * MATB + arow + mt * 16 * SROWB + kso);
                ldsm4(afl[mt], base + 1 * MATB + arow + mt * 16 * SROWB + kso);
            }
            uint32_t bfh[4][2], bfl[4][2];
#pragma unroll
            for (int nb = 0; nb < 2; nb++) {
                uint32_t t[4];
                ldsm4(t, base + 2 * MATB + brow_s + nb * 16 * SROWB + kso);
                bfh[nb * 2 + 0][0] = t[0]; bfh[nb * 2 + 0][1] = t[2];
                bfh[nb * 2 + 1][0] = t[1]; bfh[nb * 2 + 1][1] = t[3];
                ldsm4(t, base + 3 * MATB + brow_s + nb * 16 * SROWB + kso);
                bfl[nb * 2 + 0][0] = t[0]; bfl[nb * 2 + 0][1] = t[2];
                bfl[nb * 2 + 1][0] = t[1]; bfl[nb * 2 + 1][1] = t[3];
            }
#pragma unroll
            for (int mt = 0; mt < 4; mt++)
#pragma unroll
                for (int nt = 0; nt < 4; nt++) {
                    mma16816(acc[mt][nt], afh[mt], bfh[nt][0], bfh[nt][1]);
                    mma16816(acc[mt][nt], afh[mt], bfl[nt][0], bfl[nt][1]);
                    mma16816(acc[mt][nt], afl[mt], bfh[nt][0], bfh[nt][1]);
                }
        }
        __syncthreads();
    }

    const int tg = lane >> 2, tq = lane & 3;
#pragma unroll
    for (int mt = 0; mt < 4; mt++) {
        const int row = brow + wm * 64 + mt * 16 + tg;
#pragma unroll
        for (int nt = 0; nt < 4; nt++) {
            const int col = bcol + wn * 32 + nt * 8 + tq * 2;
            float b0 = 0.f, b1 = 0.f;
            if (bias) { b0 = bias[col]; b1 = bias[col + 1]; }
            *(float2*)&C[(size_t)row * Nout + col] =
                make_float2(acc[mt][nt][0] + b0, acc[mt][nt][1] + b1);
            *(float2*)&C[(size_t)(row + 8) * Nout + col] =
                make_float2(acc[mt][nt][2] + b0, acc[mt][nt][3] + b1);
        }
    }
}

// ---------------------------------------------------------------------------
// mma.sync flash attention, causal. grid (B*HEADS, SEQ/64), 128 threads.
// 4 warps x 16 query rows. S = QK^T (bf16 3-term split), softmax in f32 regs,
// O += P V (P hi/lo from S acc, V transposed in smem).
// smem: Qhi,Qlo,Khi,Klo,Vthi,Vtlo  each 64 x 144B  -> 55296 B
// ---------------------------------------------------------------------------
#define AROW 144

__global__ __launch_bounds__(128)
void flash_mma(__nv_bfloat16* __restrict__ ohi, __nv_bfloat16* __restrict__ olo)
{
    extern __shared__ char sm[];
    const uint32_t sb = smem_to_u32(sm);
    const uint32_t oQh = 0, oQl = 9216, oKh = 18432, oKl = 27648, oVh = 36864, oVl = 46080;

    const int bh = blockIdx.x;
    const int b = bh / HEADS, h = bh % HEADS;
    const int qb = blockIdx.y;
    const int tid = threadIdx.x;
    const int warp = tid >> 5, lane = tid & 31;
    const int tg = lane >> 2, tq = lane & 3;

    const float* base = g_qkv + (size_t)b * SEQ * QKV3;
    const float* Qp = base + h * DHEAD;
    const float* Kp = base + INNER + h * DHEAD;
    const float* Vp = base + 2 * INNER + h * DHEAD;

    // ---- load Q tile (scaled, split hi/lo) ----
    for (int idx = tid; idx < 1024; idx += 128) {
        const int r = idx >> 4, c4 = (idx & 15) * 4;
        float4 v = *(const float4*)(Qp + (size_t)(qb * 64 + r) * QKV3 + c4);
        v.x *= SCALE; v.y *= SCALE; v.z *= SCALE; v.w *= SCALE;
        uint32_t h0, l0, h1, l1;
        packsplit2(v.x, v.y, h0, l0);
        packsplit2(v.z, v.w, h1, l1);
        *(uint2*)(sm + oQh + r * AROW + c4 * 2) = make_uint2(h0, h1);
        *(uint2*)(sm + oQl + r * AROW + c4 * 2) = make_uint2(l0, l1);
    }
    __syncthreads();

    // ---- Q fragments (held in regs all along) ----
    uint32_t qh[4][4], ql[4][4];
    {
        const uint32_t qa = sb + (uint32_t)(warp * 16 + (lane & 15)) * AROW + ((lane >> 4) << 4);
#pragma unroll
        for (int kt = 0; kt < 4; kt++) {
            ldsm4(qh[kt], qa + oQh + kt * 32);
            ldsm4(ql[kt], qa + oQl + kt * 32);
        }
    }

    float oacc[8][4];
#pragma unroll
    for (int j = 0; j < 8; j++)
#pragma unroll
        for (int e = 0; e < 4; e++) oacc[j][e] = 0.f;
    float mrow[2] = { -1e30f, -1e30f };
    float lrow[2] = { 0.f, 0.f };

    for (int kb = 0; kb <= qb; kb++) {
        __syncthreads();  // previous K/V fully consumed
        // K tile (row-wise, split)
        for (int idx = tid; idx < 1024; idx += 128) {
            const int r = idx >> 4, c4 = (idx & 15) * 4;
            float4 v = *(const float4*)(Kp + (size_t)(kb * 64 + r) * QKV3 + c4);
            uint32_t h0, l0, h1, l1;
            packsplit2(v.x, v.y, h0, l0);
            packsplit2(v.z, v.w, h1, l1);
            *(uint2*)(sm + oKh + r * AROW + c4 * 2) = make_uint2(h0, h1);
            *(uint2*)(sm + oKl + r * AROW + c4 * 2) = make_uint2(l0, l1);
        }
        // V tile transposed: sVt[d][key]
        for (int t = tid; t < 1024; t += 128) {
            const int d = t & 63, kg = t >> 6;
            const int k0 = kg * 4;
            const float* vp = Vp + (size_t)(kb * 64 + k0) * QKV3 + d;
            float v0 = vp[0], v1 = vp[QKV3], v2 = vp[2 * QKV3], v3 = vp[3 * QKV3];
            uint32_t h0, l0, h1, l1;
            packsplit2(v0, v1, h0, l0);
            packsplit2(v2, v3, h1, l1);
            *(uint2*)(sm + oVh + d * AROW + k0 * 2) = make_uint2(h0, h1);
            *(uint2*)(sm + oVl + d * AROW + k0 * 2) = make_uint2(l0, l1);
        }
        __syncthreads();

        // ---- S = Q K^T ----
        float sacc[8][4];
#pragma unroll
        for (int j = 0; j < 8; j++)
#pragma unroll
            for (int e = 0; e < 4; e++) sacc[j][e] = 0.f;
#pragma unroll
        for (int kt = 0; kt < 4; kt++) {
#pragma unroll
            for (int kg = 0; kg < 4; kg++) {
                const uint32_t ka = sb + (uint32_t)(kg * 16 + (lane & 15)) * AROW +
                                    ((lane >> 4) << 4) + kt * 32;
                uint32_t th[4], tl[4];
                ldsm4(th, ka + oKh);
                ldsm4(tl, ka + oKl);
                mma16816(sacc[2 * kg],     qh[kt], th[0], th[2]);
                mma16816(sacc[2 * kg],     qh[kt], tl[0], tl[2]);
                mma16816(sacc[2 * kg],     ql[kt], th[0], th[2]);
                mma16816(sacc[2 * kg + 1], qh[kt], th[1], th[3]);
                mma16816(sacc[2 * kg + 1], qh[kt], tl[1], tl[3]);
                mma16816(sacc[2 * kg + 1], ql[kt], th[1], th[3]);
            }
        }

        // ---- causal mask on diagonal block ----
        if (kb == qb) {
            const int r0 = warp * 16 + tg;
#pragma unroll
            for (int j = 0; j < 8; j++) {
                const int c0 = j * 8 + tq * 2;
                if (c0     > r0)     sacc[j][0] = NEGV;
                if (c0 + 1 > r0)     sacc[j][1] = NEGV;
                if (c0     > r0 + 8) sacc[j][2] = NEGV;
                if (c0 + 1 > r0 + 8) sacc[j][3] = NEGV;
            }
        }

        // ---- online softmax (2 rows per thread) ----
#pragma unroll
        for (int rr = 0; rr < 2; rr++) {
            const int e0 = rr * 2;
            float mx = sacc[0][e0];
#pragma unroll
            for (int j = 0; j < 8; j++)
                mx = fmaxf(mx, fmaxf(sacc[j][e0], sacc[j][e0 + 1]));
            mx = fmaxf(mx, __shfl_xor_sync(0xffffffffu, mx, 1));
            mx = fmaxf(mx, __shfl_xor_sync(0xffffffffu, mx, 2));
            const float mn = fmaxf(mrow[rr], mx);
            const float corr = __expf(mrow[rr] - mn);
            float ps = 0.f;
#pragma unroll
            for (int j = 0; j < 8; j++) {
                const float p0 = __expf(sacc[j][e0] - mn);
                const float p1 = __expf(sacc[j][e0 + 1] - mn);
                sacc[j][e0] = p0; sacc[j][e0 + 1] = p1;
                ps += p0 + p1;
            }
            ps += __shfl_xor_sync(0xffffffffu, ps, 1);
            ps += __shfl_xor_sync(0xffffffffu, ps, 2);
            lrow[rr] = lrow[rr] * corr + ps;
            mrow[rr] = mn;
#pragma unroll
            for (int j = 0; j < 8; j++) {
                oacc[j][e0] *= corr; oacc[j][e0 + 1] *= corr;
            }
        }

        // ---- O += P V ----
#pragma unroll
        for (int kk = 0; kk < 4; kk++) {
            uint32_t aPh[4], aPl[4];
            packsplit2(sacc[2 * kk][0],     sacc[2 * kk][1],     aPh[0], aPl[0]);
            packsplit2(sacc[2 * kk][2],     sacc[2 * kk][3],     aPh[1], aPl[1]);
            packsplit2(sacc[2 * kk + 1][0], sacc[2 * kk + 1][1], aPh[2], aPl[2]);
            packsplit2(sacc[2 * kk + 1][2], sacc[2 * kk + 1][3], aPh[3], aPl[3]);
#pragma unroll
            for (int dg = 0; dg < 4; dg++) {
                const uint32_t va = sb + (uint32_t)(dg * 16 + (lane & 15)) * AROW +
                                    ((lane >> 4) << 4) + kk * 32;
                uint32_t vh[4], vl[4];
                ldsm4(vh, va + oVh);
                ldsm4(vl, va + oVl);
                mma16816(oacc[2 * dg],     aPh, vh[0], vh[2]);
                mma16816(oacc[2 * dg],     aPh, vl[0], vl[2]);
                mma16816(oacc[2 * dg],     aPl, vh[0], vh[2]);
                mma16816(oacc[2 * dg + 1], aPh, vh[1], vh[3]);
                mma16816(oacc[2 * dg + 1], aPh, vl[1], vl[3]);
                mma16816(oacc[2 * dg + 1], aPl, vh[1], vh[3]);
            }
        }
    }

    // ---- epilogue: normalize, split hi/lo, store ----
    const float inv0 = 1.f / lrow[0];
    const float inv1 = 1.f / lrow[1];
    const int grow0 = b * SEQ + qb * 64 + warp * 16 + tg;
    const int grow1 = grow0 + 8;
#pragma unroll
    for (int j = 0; j < 8; j++) {
        const int col = h * DHEAD + j * 8 + tq * 2;
        uint32_t hp, lp;
        packsplit2(oacc[j][0] * inv0, oacc[j][1] * inv0, hp, lp);
        *(uint32_t*)&ohi[(size_t)grow0 * INNER + col] = hp;
        *(uint32_t*)&olo[(size_t)grow0 * INNER + col] = lp;
        packsplit2(oacc[j][2] * inv1, oacc[j][3] * inv1, hp, lp);
        *(uint32_t*)&ohi[(size_t)grow1 * INNER + col] = hp;
        *(uint32_t*)&olo[(size_t)grow1 * INNER + col] = lp;
    }
}

// ---------------------------------------------------------------------------
extern "C" void kernel_launch(void* const* d_in, const int* in_sizes, int n_in,
                              void* d_out, int out_size)
{
    const float* x     = (const float*)d_in[0];
    const float* w_qkv = (const float*)d_in[1];
    const float* w_out = (const float*)d_in[2];
    const float* b_out = (const float*)d_in[3];
    float* out = (float*)d_out;

    float *qkv;
    __nv_bfloat16 *xhi, *xlo, *wqh, *wql, *woh, *wol, *ahi, *alo;
    cudaGetSymbolAddress((void**)&qkv, g_qkv);
    cudaGetSymbolAddress((void**)&xhi, g_xhi);
    cudaGetSymbolAddress((void**)&xlo, g_xlo);
    cudaGetSymbolAddress((void**)&wqh, g_wqkv_hi);
    cudaGetSymbolAddress((void**)&wql, g_wqkv_lo);
    cudaGetSymbolAddress((void**)&woh, g_wout_hi);
    cudaGetSymbolAddress((void**)&wol, g_wout_lo);
    cudaGetSymbolAddress((void**)&ahi, g_attnhi);
    cudaGetSymbolAddress((void**)&alo, g_attnlo);

    cudaFuncSetAttribute(gemm_mma,  cudaFuncAttributeMaxDynamicSharedMemorySize, 3 * BUFB);
    cudaFuncSetAttribute(flash_mma, cudaFuncAttributeMaxDynamicSharedMemorySize, 55296);

    // 1) splits
    {
        int n4 = MTOT * DIM / 4;
        split_rows<<<(n4 + 255) / 256, 256>>>(x, xhi, xlo, n4);
        split_T<<<dim3(QKV3 / 32, DIM / 32), 256>>>(w_qkv, wqh, wql, DIM, QKV3);
        split_T<<<dim3(DIM / 32, INNER / 32), 256>>>(w_out, woh, wol, INNER, DIM);
    }
    // 2) QKV projection
    gemm_mma<<<dim3(QKV3 / 128, MTOT / 128), 256, 3 * BUFB>>>(
        xhi, xlo, wqh, wql, qkv, QKV3, DIM, nullptr);
    // 3) attention (tensor-core)
    flash_mma<<<dim3(BATCH * HEADS, SEQ / 64), 128, 55296>>>(ahi, alo);
    // 4) output projection + bias
    gemm_mma<<<dim3(DIM / 128, MTOT / 128), 256, 3 * BUFB>>>(
        ahi, alo, woh, wol, out, DIM, INNER, b_out);
}

// round 7
// speedup vs baseline: 6.8263x; 1.1612x over previous
#include <cuda_runtime.h>
#include <cuda_bf16.h>
#include <cstdint>
#include <math.h>

#define BATCH 4
#define SEQ   2048
#define DIM   1024
#define HEADS 16
#define DHEAD 64
#define INNER 1024
#define QKV3  3072
#define SCALE 0.125f
#define NEGV  (-1e9f)
#define MTOT  (BATCH * SEQ)   // 8192

// ---------------------------------------------------------------------------
// Device scratch (allocation-free)
// ---------------------------------------------------------------------------
__device__ __nv_bfloat16  g_qkvhi[(size_t)MTOT * QKV3];      // 48 MB
__device__ __nv_bfloat16  g_qkvlo[(size_t)MTOT * QKV3];      // 48 MB
__device__ __nv_bfloat16  g_xhi[(size_t)MTOT * DIM];
__device__ __nv_bfloat16  g_xlo[(size_t)MTOT * DIM];
__device__ __nv_bfloat16  g_wqkv_hi[(size_t)QKV3 * DIM];     // [N][K]
__device__ __nv_bfloat16  g_wqkv_lo[(size_t)QKV3 * DIM];
__device__ __nv_bfloat16  g_wout_hi[(size_t)DIM * INNER];    // [N][K]
__device__ __nv_bfloat16  g_wout_lo[(size_t)DIM * INNER];
__device__ __nv_bfloat16  g_attnhi[(size_t)MTOT * INNER];
__device__ __nv_bfloat16  g_attnlo[(size_t)MTOT * INNER];

// ---------------------------------------------------------------------------
__device__ __forceinline__ uint32_t smem_to_u32(const void* p) {
    uint32_t a;
    asm("{ .reg .u64 t; cvta.to.shared.u64 t, %1; cvt.u32.u64 %0, t; }" : "=r"(a) : "l"(p));
    return a;
}
__device__ __forceinline__ void ldsm4(uint32_t (&r)[4], uint32_t addr) {
    asm volatile("ldmatrix.sync.aligned.m8n8.x4.shared.b16 {%0,%1,%2,%3}, [%4];"
        : "=r"(r[0]), "=r"(r[1]), "=r"(r[2]), "=r"(r[3]) : "r"(addr));
}
__device__ __forceinline__ void ldsm4t(uint32_t (&r)[4], uint32_t addr) {
    asm volatile("ldmatrix.sync.aligned.m8n8.x4.trans.shared.b16 {%0,%1,%2,%3}, [%4];"
        : "=r"(r[0]), "=r"(r[1]), "=r"(r[2]), "=r"(r[3]) : "r"(addr));
}
__device__ __forceinline__ void mma16816(float (&d)[4], const uint32_t (&a)[4],
                                         uint32_t b0, uint32_t b1) {
    asm volatile("mma.sync.aligned.m16n8k16.row.col.f32.bf16.bf16.f32 "
        "{%0,%1,%2,%3}, {%4,%5,%6,%7}, {%8,%9}, {%0,%1,%2,%3};"
        : "+f"(d[0]), "+f"(d[1]), "+f"(d[2]), "+f"(d[3])
        : "r"(a[0]), "r"(a[1]), "r"(a[2]), "r"(a[3]), "r"(b0), "r"(b1));
}
__device__ __forceinline__ void cpasync16(uint32_t dst, const void* src) {
    asm volatile("cp.async.cg.shared.global [%0], [%1], 16;" :: "r"(dst), "l"(src));
}
#define CP_COMMIT  asm volatile("cp.async.commit_group;" ::: "memory")
#define CP_WAIT1   asm volatile("cp.async.wait_group 1;" ::: "memory")
#define CP_WAIT0   asm volatile("cp.async.wait_group 0;" ::: "memory")

__device__ __forceinline__ void split2(float v, __nv_bfloat16& hi, __nv_bfloat16& lo) {
    hi = __float2bfloat16(v);
    lo = __float2bfloat16(v - __bfloat162float(hi));
}
__device__ __forceinline__ uint32_t packbf(__nv_bfloat16 a, __nv_bfloat16 b) {
    return (uint32_t)__bfloat16_as_ushort(a) | ((uint32_t)__bfloat16_as_ushort(b) << 16);
}
__device__ __forceinline__ void packsplit2(float a, float b, uint32_t& hi, uint32_t& lo) {
    __nv_bfloat16 ah, al, bh, bl;
    split2(a, ah, al); split2(b, bh, bl);
    hi = packbf(ah, bh); lo = packbf(al, bl);
}

// ---------------------------------------------------------------------------
// Conversion kernels
// ---------------------------------------------------------------------------
__global__ __launch_bounds__(256)
void split_rows(const float* __restrict__ in, __nv_bfloat16* __restrict__ hi,
                __nv_bfloat16* __restrict__ lo, int n4)
{
    int i = blockIdx.x * 256 + threadIdx.x;
    if (i >= n4) return;
    float4 v = ((const float4*)in)[i];
    __nv_bfloat16 h[4], l[4];
    split2(v.x, h[0], l[0]); split2(v.y, h[1], l[1]);
    split2(v.z, h[2], l[2]); split2(v.w, h[3], l[3]);
    uint2 hv, lv;
    hv.x = packbf(h[0], h[1]); hv.y = packbf(h[2], h[3]);
    lv.x = packbf(l[0], l[1]); lv.y = packbf(l[2], l[3]);
    ((uint2*)hi)[i] = hv;
    ((uint2*)lo)[i] = lv;
}

// in[K][N] -> out[N][K] (hi/lo)
__global__ __launch_bounds__(256)
void split_T(const float* __restrict__ in, __nv_bfloat16* __restrict__ hi,
             __nv_bfloat16* __restrict__ lo, int K, int N)
{
    __shared__ float t[32][33];
    const int k0 = blockIdx.y * 32, n0 = blockIdx.x * 32;
    const int tx = threadIdx.x & 31, ty = threadIdx.x >> 5;
#pragma unroll
    for (int i = 0; i < 32; i += 8)
        t[ty + i][tx] = in[(size_t)(k0 + ty + i) * N + n0 + tx];
    __syncthreads();
#pragma unroll
    for (int i = 0; i < 32; i += 8) {
        __nv_bfloat16 h, l;
        split2(t[tx][ty + i], h, l);
        size_t o = (size_t)(n0 + ty + i) * K + k0 + tx;
        hi[o] = h; lo[o] = l;
    }
}

// ---------------------------------------------------------------------------
// mma.sync bf16-split GEMM: C = A[M,K]*B[N,K]^T
// 128x128 block, BK=32, 8 warps, 2-stage cp.async, 2 CTAs/SM.
// Output: f32 C (+bias) if Chi==null, else bf16 hi/lo split into Chi/Clo.
// dyn smem = 2 * 40960 = 81920 B
// ---------------------------------------------------------------------------
#define SROWB 80
#define MATB  (128 * SROWB)       // 10240
#define BUFB  (4 * MATB)          // 40960

__global__ __launch_bounds__(256, 2)
void gemm_mma(const __nv_bfloat16* __restrict__ Ahi, const __nv_bfloat16* __restrict__ Alo,
              const __nv_bfloat16* __restrict__ Bhi, const __nv_bfloat16* __restrict__ Blo,
              float* __restrict__ C, __nv_bfloat16* __restrict__ Chi,
              __nv_bfloat16* __restrict__ Clo,
              int Nout, int K, const float* __restrict__ bias)
{
    extern __shared__ char sm[];
    const uint32_t sb = smem_to_u32(sm);
    const int tid = threadIdx.x;
    const int wid = tid >> 5, lane = tid & 31;
    const int wm = wid >> 2, wn = wid & 3;
    const int brow = blockIdx.y * 128, bcol = blockIdx.x * 128;

    const __nv_bfloat16* gsrc[4] = {
        Ahi + (size_t)brow * K, Alo + (size_t)brow * K,
        Bhi + (size_t)bcol * K, Blo + (size_t)bcol * K };

    const int r0 = tid >> 2;
    const int kh = (tid & 3) * 8;
    const int nch = K / 32;

    float acc[4][4][4];
#pragma unroll
    for (int mt = 0; mt < 4; mt++)
#pragma unroll
        for (int nt = 0; nt < 4; nt++)
#pragma unroll
            for (int i = 0; i < 4; i++) acc[mt][nt][i] = 0.f;

    auto issue = [&](int c) {
        const uint32_t d = sb + (uint32_t)(c & 1) * BUFB;
        const int koff = c * 32 + kh;
#pragma unroll
        for (int m = 0; m < 4; m++)
#pragma unroll
            for (int s = 0; s < 2; s++)
                cpasync16(d + m * MATB + (r0 + s * 64) * SROWB + kh * 2,
                          gsrc[m] + (size_t)(r0 + s * 64) * K + koff);
    };

    issue(0); CP_COMMIT;

    const uint32_t arow  = (uint32_t)(wm * 64 + (lane & 15)) * SROWB + (lane >> 4) * 16;
    const uint32_t brow_s = (uint32_t)(wn * 32 + (lane & 15)) * SROWB + (lane >> 4) * 16;

    for (int c = 0; c < nch; c++) {
        if (c + 1 < nch) { issue(c + 1); CP_COMMIT; CP_WAIT1; }
        else             { CP_WAIT0; }
        __syncthreads();
        const uint32_t base = sb + (uint32_t)(c & 1) * BUFB;
#pragma unroll
        for (int ks = 0; ks < 2; ks++) {
            const uint32_t kso = ks * 32;
            uint32_t afh[4][4], afl[4][4];
#pragma unroll
            for (int mt = 0; mt < 4; mt++) {
                ldsm4(afh[mt], base + 0 * MATB + arow + mt * 16 * SROWB + kso);
                ldsm4(afl[mt], base + 1 * MATB + arow + mt * 16 * SROWB + kso);
            }
            uint32_t bfh[4][2], bfl[4][2];
#pragma unroll
            for (int nb = 0; nb < 2; nb++) {
                uint32_t t[4];
                ldsm4(t, base + 2 * MATB + brow_s + nb * 16 * SROWB + kso);
                bfh[nb * 2 + 0][0] = t[0]; bfh[nb * 2 + 0][1] = t[2];
                bfh[nb * 2 + 1][0] = t[1]; bfh[nb * 2 + 1][1] = t[3];
                ldsm4(t, base + 3 * MATB + brow_s + nb * 16 * SROWB + kso);
                bfl[nb * 2 + 0][0] = t[0]; bfl[nb * 2 + 0][1] = t[2];
                bfl[nb * 2 + 1][0] = t[1]; bfl[nb * 2 + 1][1] = t[3];
            }
#pragma unroll
            for (int mt = 0; mt < 4; mt++)
#pragma unroll
                for (int nt = 0; nt < 4; nt++) {
                    mma16816(acc[mt][nt], afh[mt], bfh[nt][0], bfh[nt][1]);
                    mma16816(acc[mt][nt], afh[mt], bfl[nt][0], bfl[nt][1]);
                    mma16816(acc[mt][nt], afl[mt], bfh[nt][0], bfh[nt][1]);
                }
        }
        __syncthreads();
    }

    const int tg = lane >> 2, tq = lane & 3;
    if (Chi) {
        // bf16 hi/lo split output
#pragma unroll
        for (int mt = 0; mt < 4; mt++) {
            const int row = brow + wm * 64 + mt * 16 + tg;
#pragma unroll
            for (int nt = 0; nt < 4; nt++) {
                const int col = bcol + wn * 32 + nt * 8 + tq * 2;
                uint32_t hp, lp;
                packsplit2(acc[mt][nt][0], acc[mt][nt][1], hp, lp);
                *(uint32_t*)&Chi[(size_t)row * Nout + col] = hp;
                *(uint32_t*)&Clo[(size_t)row * Nout + col] = lp;
                packsplit2(acc[mt][nt][2], acc[mt][nt][3], hp, lp);
                *(uint32_t*)&Chi[(size_t)(row + 8) * Nout + col] = hp;
                *(uint32_t*)&Clo[(size_t)(row + 8) * Nout + col] = lp;
            }
        }
    } else {
#pragma unroll
        for (int mt = 0; mt < 4; mt++) {
            const int row = brow + wm * 64 + mt * 16 + tg;
#pragma unroll
            for (int nt = 0; nt < 4; nt++) {
                const int col = bcol + wn * 32 + nt * 8 + tq * 2;
                float b0 = 0.f, b1 = 0.f;
                if (bias) { b0 = bias[col]; b1 = bias[col + 1]; }
                *(float2*)&C[(size_t)row * Nout + col] =
                    make_float2(acc[mt][nt][0] + b0, acc[mt][nt][1] + b1);
                *(float2*)&C[(size_t)(row + 8) * Nout + col] =
                    make_float2(acc[mt][nt][2] + b0, acc[mt][nt][3] + b1);
            }
        }
    }
}

// ---------------------------------------------------------------------------
// mma.sync flash attention, causal, pre-split bf16 inputs, cp.async loaders.
// grid (B*HEADS, SEQ/64), 128 threads. V via ldmatrix.trans.
// smem: Qhi,Qlo (2 x 9216) + 2 stages x (Khi,Klo,Vhi,Vlo) (4 x 9216) = 92160 B
// ---------------------------------------------------------------------------
#define VROWB 144
#define TILEB 9216                 // 64 * 144
#define STAGEB (4 * TILEB)         // 36864

__global__ __launch_bounds__(128)
void flash_mma(__nv_bfloat16* __restrict__ ohi, __nv_bfloat16* __restrict__ olo)
{
    extern __shared__ char sm[];
    const uint32_t sb = smem_to_u32(sm);
    const uint32_t oQh = 0, oQl = TILEB, oStage = 2 * TILEB;

    const int bh = blockIdx.x;
    const int b = bh / HEADS, h = bh % HEADS;
    const int qb = blockIdx.y;
    const int tid = threadIdx.x;
    const int warp = tid >> 5, lane = tid & 31;
    const int tg = lane >> 2, tq = lane & 3;

    const size_t rowbase = (size_t)(b * SEQ) * QKV3;
    const __nv_bfloat16* Qh = g_qkvhi + rowbase + h * DHEAD;
    const __nv_bfloat16* Ql = g_qkvlo + rowbase + h * DHEAD;
    const __nv_bfloat16* Kh = Qh + INNER;
    const __nv_bfloat16* Kl = Ql + INNER;
    const __nv_bfloat16* Vh = Qh + 2 * INNER;
    const __nv_bfloat16* Vl = Ql + 2 * INNER;

    // issue K/V tiles for block kb2 into stage s
    auto issue_kv = [&](int kb2, int s) {
        const uint32_t st = sb + oStage + (uint32_t)s * STAGEB;
        const __nv_bfloat16* srcs[4] = {
            Kh + (size_t)(kb2 * 64) * QKV3, Kl + (size_t)(kb2 * 64) * QKV3,
            Vh + (size_t)(kb2 * 64) * QKV3, Vl + (size_t)(kb2 * 64) * QKV3 };
#pragma unroll
        for (int i = 0; i < 4; i++)
#pragma unroll
            for (int j = 0; j < 4; j++) {
                const int idx = tid + j * 128;
                const int r = idx >> 3, ch = idx & 7;
                cpasync16(st + i * TILEB + r * VROWB + ch * 16,
                          srcs[i] + (size_t)r * QKV3 + ch * 8);
            }
    };

    issue_kv(0, 0); CP_COMMIT;

    // ---- Q tile: plain loads (once) ----
    for (int idx = tid; idx < 512; idx += 128) {
        const int r = idx >> 2, ch = idx & 3;   // 4 x 16B chunks per row... (128B row)
        // row = r (0..63 via 512/8?) -- recompute: 64 rows x 8 chunks = 512
    }
    // (corrected loader below)
    for (int idx = tid; idx < 512; idx += 128) {
        const int r = idx >> 3, ch = idx & 7;
        const size_t src = (size_t)(qb * 64 + r) * QKV3 + ch * 8;
        *(uint4*)(sm + oQh + r * VROWB + ch * 16) = *(const uint4*)(Qh + src);
        *(uint4*)(sm + oQl + r * VROWB + ch * 16) = *(const uint4*)(Ql + src);
    }
    __syncthreads();

    // ---- Q fragments in regs ----
    uint32_t qh[4][4], ql[4][4];
    {
        const uint32_t qa = sb + (uint32_t)(warp * 16 + (lane & 15)) * VROWB + ((lane >> 4) << 4);
#pragma unroll
        for (int kt = 0; kt < 4; kt++) {
            ldsm4(qh[kt], qa + oQh + kt * 32);
            ldsm4(ql[kt], qa + oQl + kt * 32);
        }
    }

    float oacc[8][4];
#pragma unroll
    for (int j = 0; j < 8; j++)
#pragma unroll
        for (int e = 0; e < 4; e++) oacc[j][e] = 0.f;
    float mrow[2] = { -1e30f, -1e30f };
    float lrow[2] = { 0.f, 0.f };

    for (int kb = 0; kb <= qb; kb++) {
        const int s = kb & 1;
        if (kb < qb) { issue_kv(kb + 1, s ^ 1); CP_COMMIT; CP_WAIT1; }
        else         { CP_WAIT0; }
        __syncthreads();
        const uint32_t stK = sb + oStage + (uint32_t)s * STAGEB;
        const uint32_t stV = stK + 2 * TILEB;

        // ---- S = Q K^T ----
        float sacc[8][4];
#pragma unroll
        for (int j = 0; j < 8; j++)
#pragma unroll
            for (int e = 0; e < 4; e++) sacc[j][e] = 0.f;
#pragma unroll
        for (int kt = 0; kt < 4; kt++) {
#pragma unroll
            for (int kg = 0; kg < 4; kg++) {
                const uint32_t ka = stK + (uint32_t)(kg * 16 + (lane & 15)) * VROWB +
                                    ((lane >> 4) << 4) + kt * 32;
                uint32_t th[4], tl[4];
                ldsm4(th, ka);
                ldsm4(tl, ka + TILEB);
                mma16816(sacc[2 * kg],     qh[kt], th[0], th[2]);
                mma16816(sacc[2 * kg],     qh[kt], tl[0], tl[2]);
                mma16816(sacc[2 * kg],     ql[kt], th[0], th[2]);
                mma16816(sacc[2 * kg + 1], qh[kt], th[1], th[3]);
                mma16816(sacc[2 * kg + 1], qh[kt], tl[1], tl[3]);
                mma16816(sacc[2 * kg + 1], ql[kt], th[1], th[3]);
            }
        }

        // ---- scale ----
#pragma unroll
        for (int j = 0; j < 8; j++)
#pragma unroll
            for (int e = 0; e < 4; e++) sacc[j][e] *= SCALE;

        // ---- causal mask on diagonal block ----
        if (kb == qb) {
            const int r0 = warp * 16 + tg;
#pragma unroll
            for (int j = 0; j < 8; j++) {
                const int c0 = j * 8 + tq * 2;
                if (c0     > r0)     sacc[j][0] = NEGV;
                if (c0 + 1 > r0)     sacc[j][1] = NEGV;
                if (c0     > r0 + 8) sacc[j][2] = NEGV;
                if (c0 + 1 > r0 + 8) sacc[j][3] = NEGV;
            }
        }

        // ---- online softmax (2 rows per thread) ----
#pragma unroll
        for (int rr = 0; rr < 2; rr++) {
            const int e0 = rr * 2;
            float mx = sacc[0][e0];
#pragma unroll
            for (int j = 0; j < 8; j++)
                mx = fmaxf(mx, fmaxf(sacc[j][e0], sacc[j][e0 + 1]));
            mx = fmaxf(mx, __shfl_xor_sync(0xffffffffu, mx, 1));
            mx = fmaxf(mx, __shfl_xor_sync(0xffffffffu, mx, 2));
            const float mn = fmaxf(mrow[rr], mx);
            const float corr = __expf(mrow[rr] - mn);
            float ps = 0.f;
#pragma unroll
            for (int j = 0; j < 8; j++) {
                const float p0 = __expf(sacc[j][e0] - mn);
                const float p1 = __expf(sacc[j][e0 + 1] - mn);
                sacc[j][e0] = p0; sacc[j][e0 + 1] = p1;
                ps += p0 + p1;
            }
            ps += __shfl_xor_sync(0xffffffffu, ps, 1);
            ps += __shfl_xor_sync(0xffffffffu, ps, 2);
            lrow[rr] = lrow[rr] * corr + ps;
            mrow[rr] = mn;
#pragma unroll
            for (int j = 0; j < 8; j++) {
                oacc[j][e0] *= corr; oacc[j][e0 + 1] *= corr;
            }
        }

        // ---- O += P V (V via ldsm.trans) ----
#pragma unroll
        for (int kk = 0; kk < 4; kk++) {
            uint32_t aPh[4], aPl[4];
            packsplit2(sacc[2 * kk][0],     sacc[2 * kk][1],     aPh[0], aPl[0]);
            packsplit2(sacc[2 * kk][2],     sacc[2 * kk][3],     aPh[1], aPl[1]);
            packsplit2(sacc[2 * kk + 1][0], sacc[2 * kk + 1][1], aPh[2], aPl[2]);
            packsplit2(sacc[2 * kk + 1][2], sacc[2 * kk + 1][3], aPh[3], aPl[3]);
#pragma unroll
            for (int dg = 0; dg < 4; dg++) {
                const uint32_t va = stV + (uint32_t)(kk * 16 + (lane & 15)) * VROWB +
                                    ((lane >> 4) << 4) + dg * 32;
                uint32_t vh[4], vl[4];
                ldsm4t(vh, va);
                ldsm4t(vl, va + TILEB);
                mma16816(oacc[2 * dg],     aPh, vh[0], vh[1]);
                mma16816(oacc[2 * dg],     aPh, vl[0], vl[1]);
                mma16816(oacc[2 * dg],     aPl, vh[0], vh[1]);
                mma16816(oacc[2 * dg + 1], aPh, vh[2], vh[3]);
                mma16816(oacc[2 * dg + 1], aPh, vl[2], vl[3]);
                mma16816(oacc[2 * dg + 1], aPl, vh[2], vh[3]);
            }
        }
        __syncthreads();  // all warps done with stage s before it is refilled
    }

    // ---- epilogue ----
    const float inv0 = 1.f / lrow[0];
    const float inv1 = 1.f / lrow[1];
    const int grow0 = b * SEQ + qb * 64 + warp * 16 + tg;
    const int grow1 = grow0 + 8;
#pragma unroll
    for (int j = 0; j < 8; j++) {
        const int col = h * DHEAD + j * 8 + tq * 2;
        uint32_t hp, lp;
        packsplit2(oacc[j][0] * inv0, oacc[j][1] * inv0, hp, lp);
        *(uint32_t*)&ohi[(size_t)grow0 * INNER + col] = hp;
        *(uint32_t*)&olo[(size_t)grow0 * INNER + col] = lp;
        packsplit2(oacc[j][2] * inv1, oacc[j][3] * inv1, hp, lp);
        *(uint32_t*)&ohi[(size_t)grow1 * INNER + col] = hp;
        *(uint32_t*)&olo[(size_t)grow1 * INNER + col] = lp;
    }
}

// ---------------------------------------------------------------------------
extern "C" void kernel_launch(void* const* d_in, const int* in_sizes, int n_in,
                              void* d_out, int out_size)
{
    const float* x     = (const float*)d_in[0];
    const float* w_qkv = (const float*)d_in[1];
    const float* w_out = (const float*)d_in[2];
    const float* b_out = (const float*)d_in[3];
    float* out = (float*)d_out;

    __nv_bfloat16 *qh, *qlo, *xhi, *xlo, *wqh, *wql, *woh, *wol, *ahi, *alo;
    cudaGetSymbolAddress((void**)&qh,  g_qkvhi);
    cudaGetSymbolAddress((void**)&qlo, g_qkvlo);
    cudaGetSymbolAddress((void**)&xhi, g_xhi);
    cudaGetSymbolAddress((void**)&xlo, g_xlo);
    cudaGetSymbolAddress((void**)&wqh, g_wqkv_hi);
    cudaGetSymbolAddress((void**)&wql, g_wqkv_lo);
    cudaGetSymbolAddress((void**)&woh, g_wout_hi);
    cudaGetSymbolAddress((void**)&wol, g_wout_lo);
    cudaGetSymbolAddress((void**)&ahi, g_attnhi);
    cudaGetSymbolAddress((void**)&alo, g_attnlo);

    cudaFuncSetAttribute(gemm_mma,  cudaFuncAttributeMaxDynamicSharedMemorySize, 2 * BUFB);
    cudaFuncSetAttribute(flash_mma, cudaFuncAttributeMaxDynamicSharedMemorySize,
                         2 * TILEB + 2 * STAGEB);

    // 1) splits
    {
        int n4 = MTOT * DIM / 4;
        split_rows<<<(n4 + 255) / 256, 256>>>(x, xhi, xlo, n4);
        split_T<<<dim3(QKV3 / 32, DIM / 32), 256>>>(w_qkv, wqh, wql, DIM, QKV3);
        split_T<<<dim3(DIM / 32, INNER / 32), 256>>>(w_out, woh, wol, INNER, DIM);
    }
    // 2) QKV projection -> bf16 hi/lo
    gemm_mma<<<dim3(QKV3 / 128, MTOT / 128), 256, 2 * BUFB>>>(
        xhi, xlo, wqh, wql, nullptr, qh, qlo, QKV3, DIM, nullptr);
    // 3) attention (tensor-core, pre-split inputs)
    flash_mma<<<dim3(BATCH * HEADS, SEQ / 64), 128, 2 * TILEB + 2 * STAGEB>>>(ahi, alo);
    // 4) output projection + bias (f32)
    gemm_mma<<<dim3(DIM / 128, MTOT / 128), 256, 2 * BUFB>>>(
        ahi, alo, woh, wol, out, nullptr, nullptr, DIM, INNER, b_out);
}

// round 8
// speedup vs baseline: 6.9637x; 1.0201x over previous
#include <cuda_runtime.h>
#include <cuda_bf16.h>
#include <cstdint>
#include <math.h>

#define BATCH 4
#define SEQ   2048
#define DIM   1024
#define HEADS 16
#define DHEAD 64
#define INNER 1024
#define QKV3  3072
#define SCALE 0.125f
#define NEGV  (-1e9f)
#define MTOT  (BATCH * SEQ)   // 8192

// ---------------------------------------------------------------------------
// Device scratch (allocation-free)
// ---------------------------------------------------------------------------
__device__ __nv_bfloat16  g_qkvhi[(size_t)MTOT * QKV3];      // 48 MB
__device__ __nv_bfloat16  g_qkvlo[(size_t)MTOT * QKV3];      // 48 MB
__device__ __nv_bfloat16  g_xhi[(size_t)MTOT * DIM];
__device__ __nv_bfloat16  g_xlo[(size_t)MTOT * DIM];
__device__ __nv_bfloat16  g_wqkv_hi[(size_t)QKV3 * DIM];     // [N][K]
__device__ __nv_bfloat16  g_wqkv_lo[(size_t)QKV3 * DIM];
__device__ __nv_bfloat16  g_wout_hi[(size_t)DIM * INNER];    // [N][K]
__device__ __nv_bfloat16  g_wout_lo[(size_t)DIM * INNER];
__device__ __nv_bfloat16  g_attnhi[(size_t)MTOT * INNER];
__device__ __nv_bfloat16  g_attnlo[(size_t)MTOT * INNER];

// ---------------------------------------------------------------------------
__device__ __forceinline__ uint32_t smem_to_u32(const void* p) {
    uint32_t a;
    asm("{ .reg .u64 t; cvta.to.shared.u64 t, %1; cvt.u32.u64 %0, t; }" : "=r"(a) : "l"(p));
    return a;
}
__device__ __forceinline__ void ldsm4(uint32_t (&r)[4], uint32_t addr) {
    asm volatile("ldmatrix.sync.aligned.m8n8.x4.shared.b16 {%0,%1,%2,%3}, [%4];"
        : "=r"(r[0]), "=r"(r[1]), "=r"(r[2]), "=r"(r[3]) : "r"(addr));
}
__device__ __forceinline__ void ldsm4t(uint32_t (&r)[4], uint32_t addr) {
    asm volatile("ldmatrix.sync.aligned.m8n8.x4.trans.shared.b16 {%0,%1,%2,%3}, [%4];"
        : "=r"(r[0]), "=r"(r[1]), "=r"(r[2]), "=r"(r[3]) : "r"(addr));
}
__device__ __forceinline__ void mma16816(float (&d)[4], const uint32_t (&a)[4],
                                         uint32_t b0, uint32_t b1) {
    asm volatile("mma.sync.aligned.m16n8k16.row.col.f32.bf16.bf16.f32 "
        "{%0,%1,%2,%3}, {%4,%5,%6,%7}, {%8,%9}, {%0,%1,%2,%3};"
        : "+f"(d[0]), "+f"(d[1]), "+f"(d[2]), "+f"(d[3])
        : "r"(a[0]), "r"(a[1]), "r"(a[2]), "r"(a[3]), "r"(b0), "r"(b1));
}
__device__ __forceinline__ void cpasync16(uint32_t dst, const void* src) {
    asm volatile("cp.async.cg.shared.global [%0], [%1], 16;" :: "r"(dst), "l"(src));
}
#define CP_COMMIT  asm volatile("cp.async.commit_group;" ::: "memory")
#define CP_WAIT1   asm volatile("cp.async.wait_group 1;" ::: "memory")
#define CP_WAIT0   asm volatile("cp.async.wait_group 0;" ::: "memory")

__device__ __forceinline__ void split2(float v, __nv_bfloat16& hi, __nv_bfloat16& lo) {
    hi = __float2bfloat16(v);
    lo = __float2bfloat16(v - __bfloat162float(hi));
}
__device__ __forceinline__ uint32_t packbf(__nv_bfloat16 a, __nv_bfloat16 b) {
    return (uint32_t)__bfloat16_as_ushort(a) | ((uint32_t)__bfloat16_as_ushort(b) << 16);
}
__device__ __forceinline__ void packsplit2(float a, float b, uint32_t& hi, uint32_t& lo) {
    __nv_bfloat16 ah, al, bh, bl;
    split2(a, ah, al); split2(b, bh, bl);
    hi = packbf(ah, bh); lo = packbf(al, bl);
}

// ---------------------------------------------------------------------------
// Conversion kernels
// ---------------------------------------------------------------------------
__global__ __launch_bounds__(256)
void split_rows(const float* __restrict__ in, __nv_bfloat16* __restrict__ hi,
                __nv_bfloat16* __restrict__ lo, int n4)
{
    int i = blockIdx.x * 256 + threadIdx.x;
    if (i >= n4) return;
    float4 v = ((const float4*)in)[i];
    __nv_bfloat16 h[4], l[4];
    split2(v.x, h[0], l[0]); split2(v.y, h[1], l[1]);
    split2(v.z, h[2], l[2]); split2(v.w, h[3], l[3]);
    uint2 hv, lv;
    hv.x = packbf(h[0], h[1]); hv.y = packbf(h[2], h[3]);
    lv.x = packbf(l[0], l[1]); lv.y = packbf(l[2], l[3]);
    ((uint2*)hi)[i] = hv;
    ((uint2*)lo)[i] = lv;
}

// in[K][N] -> out[N][K] (hi/lo)
__global__ __launch_bounds__(256)
void split_T(const float* __restrict__ in, __nv_bfloat16* __restrict__ hi,
             __nv_bfloat16* __restrict__ lo, int K, int N)
{
    __shared__ float t[32][33];
    const int k0 = blockIdx.y * 32, n0 = blockIdx.x * 32;
    const int tx = threadIdx.x & 31, ty = threadIdx.x >> 5;
#pragma unroll
    for (int i = 0; i < 32; i += 8)
        t[ty + i][tx] = in[(size_t)(k0 + ty + i) * N + n0 + tx];
    __syncthreads();
#pragma unroll
    for (int i = 0; i < 32; i += 8) {
        __nv_bfloat16 h, l;
        split2(t[tx][ty + i], h, l);
        size_t o = (size_t)(n0 + ty + i) * K + k0 + tx;
        hi[o] = h; lo[o] = l;
    }
}

// ---------------------------------------------------------------------------
// mma.sync bf16-split GEMM: C = A[M,K]*B[N,K]^T
// 128x128 block, BK=32, 8 warps, 2-stage cp.async, 2 CTAs/SM.
// Term-major mma ordering: 16 independent mma between same-acc reuses.
// ---------------------------------------------------------------------------
#define SROWB 80
#define MATB  (128 * SROWB)       // 10240
#define BUFB  (4 * MATB)          // 40960

__global__ __launch_bounds__(256, 2)
void gemm_mma(const __nv_bfloat16* __restrict__ Ahi, const __nv_bfloat16* __restrict__ Alo,
              const __nv_bfloat16* __restrict__ Bhi, const __nv_bfloat16* __restrict__ Blo,
              float* __restrict__ C, __nv_bfloat16* __restrict__ Chi,
              __nv_bfloat16* __restrict__ Clo,
              int Nout, int K, const float* __restrict__ bias)
{
    extern __shared__ char sm[];
    const uint32_t sb = smem_to_u32(sm);
    const int tid = threadIdx.x;
    const int wid = tid >> 5, lane = tid & 31;
    const int wm = wid >> 2, wn = wid & 3;
    const int brow = blockIdx.y * 128, bcol = blockIdx.x * 128;

    const __nv_bfloat16* gsrc[4] = {
        Ahi + (size_t)brow * K, Alo + (size_t)brow * K,
        Bhi + (size_t)bcol * K, Blo + (size_t)bcol * K };

    const int r0 = tid >> 2;
    const int kh = (tid & 3) * 8;
    const int nch = K / 32;

    float acc[4][4][4];
#pragma unroll
    for (int mt = 0; mt < 4; mt++)
#pragma unroll
        for (int nt = 0; nt < 4; nt++)
#pragma unroll
            for (int i = 0; i < 4; i++) acc[mt][nt][i] = 0.f;

    auto issue = [&](int c) {
        const uint32_t d = sb + (uint32_t)(c & 1) * BUFB;
        const int koff = c * 32 + kh;
#pragma unroll
        for (int m = 0; m < 4; m++)
#pragma unroll
            for (int s = 0; s < 2; s++)
                cpasync16(d + m * MATB + (r0 + s * 64) * SROWB + kh * 2,
                          gsrc[m] + (size_t)(r0 + s * 64) * K + koff);
    };

    issue(0); CP_COMMIT;

    const uint32_t arow  = sb + (uint32_t)(wm * 64 + (lane & 15)) * SROWB + (lane >> 4) * 16;
    const uint32_t brow_s = sb + (uint32_t)(wn * 32 + (lane & 15)) * SROWB + (lane >> 4) * 16;

    for (int c = 0; c < nch; c++) {
        if (c + 1 < nch) { issue(c + 1); CP_COMMIT; CP_WAIT1; }
        else             { CP_WAIT0; }
        __syncthreads();
        const uint32_t boff = (uint32_t)(c & 1) * BUFB;
#pragma unroll
        for (int ks = 0; ks < 2; ks++) {
            const uint32_t kso = boff + ks * 32;
            uint32_t afh[4][4], afl[4][4];
#pragma unroll
            for (int mt = 0; mt < 4; mt++) {
                ldsm4(afh[mt], arow + 0 * MATB + mt * 16 * SROWB + kso);
                ldsm4(afl[mt], arow + 1 * MATB + mt * 16 * SROWB + kso);
            }
            uint32_t bfh[4][2], bfl[4][2];
#pragma unroll
            for (int nb = 0; nb < 2; nb++) {
                uint32_t t[4];
                ldsm4(t, brow_s + 2 * MATB + nb * 16 * SROWB + kso);
                bfh[nb * 2 + 0][0] = t[0]; bfh[nb * 2 + 0][1] = t[2];
                bfh[nb * 2 + 1][0] = t[1]; bfh[nb * 2 + 1][1] = t[3];
                ldsm4(t, brow_s + 3 * MATB + nb * 16 * SROWB + kso);
                bfl[nb * 2 + 0][0] = t[0]; bfl[nb * 2 + 0][1] = t[2];
                bfl[nb * 2 + 1][0] = t[1]; bfl[nb * 2 + 1][1] = t[3];
            }
            // term-major: each acc revisited only after 16 other mma
#pragma unroll
            for (int mt = 0; mt < 4; mt++)
#pragma unroll
                for (int nt = 0; nt < 4; nt++)
                    mma16816(acc[mt][nt], afh[mt], bfh[nt][0], bfh[nt][1]);
#pragma unroll
            for (int mt = 0; mt < 4; mt++)
#pragma unroll
                for (int nt = 0; nt < 4; nt++)
                    mma16816(acc[mt][nt], afh[mt], bfl[nt][0], bfl[nt][1]);
#pragma unroll
            for (int mt = 0; mt < 4; mt++)
#pragma unroll
                for (int nt = 0; nt < 4; nt++)
                    mma16816(acc[mt][nt], afl[mt], bfh[nt][0], bfh[nt][1]);
        }
        __syncthreads();
    }

    const int tg = lane >> 2, tq = lane & 3;
    if (Chi) {
#pragma unroll
        for (int mt = 0; mt < 4; mt++) {
            const int row = brow + wm * 64 + mt * 16 + tg;
#pragma unroll
            for (int nt = 0; nt < 4; nt++) {
                const int col = bcol + wn * 32 + nt * 8 + tq * 2;
                uint32_t hp, lp;
                packsplit2(acc[mt][nt][0], acc[mt][nt][1], hp, lp);
                *(uint32_t*)&Chi[(size_t)row * Nout + col] = hp;
                *(uint32_t*)&Clo[(size_t)row * Nout + col] = lp;
                packsplit2(acc[mt][nt][2], acc[mt][nt][3], hp, lp);
                *(uint32_t*)&Chi[(size_t)(row + 8) * Nout + col] = hp;
                *(uint32_t*)&Clo[(size_t)(row + 8) * Nout + col] = lp;
            }
        }
    } else {
#pragma unroll
        for (int mt = 0; mt < 4; mt++) {
            const int row = brow + wm * 64 + mt * 16 + tg;
#pragma unroll
            for (int nt = 0; nt < 4; nt++) {
                const int col = bcol + wn * 32 + nt * 8 + tq * 2;
                float b0 = 0.f, b1 = 0.f;
                if (bias) { b0 = bias[col]; b1 = bias[col + 1]; }
                *(float2*)&C[(size_t)row * Nout + col] =
                    make_float2(acc[mt][nt][0] + b0, acc[mt][nt][1] + b1);
                *(float2*)&C[(size_t)(row + 8) * Nout + col] =
                    make_float2(acc[mt][nt][2] + b0, acc[mt][nt][3] + b1);
            }
        }
    }
}

// ---------------------------------------------------------------------------
// mma.sync flash attention, causal, pre-split bf16 inputs, cp.async loaders.
// grid (B*HEADS, SEQ/64), 128 threads. Paired-fragment mma ordering.
// smem: Qhi,Qlo (2 x 9216) + 2 stages x (Khi,Klo,Vhi,Vlo) = 92160 B
// ---------------------------------------------------------------------------
#define VROWB 144
#define TILEB 9216                 // 64 * 144
#define STAGEB (4 * TILEB)         // 36864

__global__ __launch_bounds__(128)
void flash_mma(__nv_bfloat16* __restrict__ ohi, __nv_bfloat16* __restrict__ olo)
{
    extern __shared__ char sm[];
    const uint32_t sb = smem_to_u32(sm);
    const uint32_t oQh = 0, oQl = TILEB, oStage = 2 * TILEB;

    const int bh = blockIdx.x;
    const int b = bh / HEADS, h = bh % HEADS;
    const int qb = blockIdx.y;
    const int tid = threadIdx.x;
    const int warp = tid >> 5, lane = tid & 31;
    const int tg = lane >> 2, tq = lane & 3;

    const size_t rowbase = (size_t)(b * SEQ) * QKV3;
    const __nv_bfloat16* Qh = g_qkvhi + rowbase + h * DHEAD;
    const __nv_bfloat16* Ql = g_qkvlo + rowbase + h * DHEAD;
    const __nv_bfloat16* Kh = Qh + INNER;
    const __nv_bfloat16* Kl = Ql + INNER;
    const __nv_bfloat16* Vh = Qh + 2 * INNER;
    const __nv_bfloat16* Vl = Ql + 2 * INNER;

    auto issue_kv = [&](int kb2, int s) {
        const uint32_t st = sb + oStage + (uint32_t)s * STAGEB;
        const __nv_bfloat16* srcs[4] = {
            Kh + (size_t)(kb2 * 64) * QKV3, Kl + (size_t)(kb2 * 64) * QKV3,
            Vh + (size_t)(kb2 * 64) * QKV3, Vl + (size_t)(kb2 * 64) * QKV3 };
#pragma unroll
        for (int i = 0; i < 4; i++)
#pragma unroll
            for (int j = 0; j < 4; j++) {
                const int idx = tid + j * 128;
                const int r = idx >> 3, ch = idx & 7;
                cpasync16(st + i * TILEB + r * VROWB + ch * 16,
                          srcs[i] + (size_t)r * QKV3 + ch * 8);
            }
    };

    issue_kv(0, 0); CP_COMMIT;

    // ---- Q tile: plain loads (once) ----
    for (int idx = tid; idx < 512; idx += 128) {
        const int r = idx >> 3, ch = idx & 7;
        const size_t src = (size_t)(qb * 64 + r) * QKV3 + ch * 8;
        *(uint4*)(sm + oQh + r * VROWB + ch * 16) = *(const uint4*)(Qh + src);
        *(uint4*)(sm + oQl + r * VROWB + ch * 16) = *(const uint4*)(Ql + src);
    }
    __syncthreads();

    // ---- Q fragments in regs ----
    uint32_t qh[4][4], ql[4][4];
    {
        const uint32_t qa = sb + (uint32_t)(warp * 16 + (lane & 15)) * VROWB + ((lane >> 4) << 4);
#pragma unroll
        for (int kt = 0; kt < 4; kt++) {
            ldsm4(qh[kt], qa + oQh + kt * 32);
            ldsm4(ql[kt], qa + oQl + kt * 32);
        }
    }

    float oacc[8][4];
#pragma unroll
    for (int j = 0; j < 8; j++)
#pragma unroll
        for (int e = 0; e < 4; e++) oacc[j][e] = 0.f;
    float mrow[2] = { -1e30f, -1e30f };
    float lrow[2] = { 0.f, 0.f };

    const uint32_t fragoff = (uint32_t)(lane & 15) * VROWB + ((lane >> 4) << 4);

    for (int kb = 0; kb <= qb; kb++) {
        const int s = kb & 1;
        if (kb < qb) { issue_kv(kb + 1, s ^ 1); CP_COMMIT; CP_WAIT1; }
        else         { CP_WAIT0; }
        __syncthreads();
        const uint32_t stK = sb + oStage + (uint32_t)s * STAGEB;
        const uint32_t stV = stK + 2 * TILEB;

        // ---- S = Q K^T (kg pairs; term-major inside pair) ----
        float sacc[8][4];
#pragma unroll
        for (int j = 0; j < 8; j++)
#pragma unroll
            for (int e = 0; e < 4; e++) sacc[j][e] = 0.f;
#pragma unroll
        for (int kt = 0; kt < 4; kt++) {
#pragma unroll
            for (int kp = 0; kp < 2; kp++) {      // kg pair {2kp, 2kp+1}
                uint32_t th[2][4], tl[2][4];
#pragma unroll
                for (int u = 0; u < 2; u++) {
                    const uint32_t ka = stK + (uint32_t)((2 * kp + u) * 16) * VROWB +
                                        fragoff + kt * 32;
                    ldsm4(th[u], ka);
                    ldsm4(tl[u], ka + TILEB);
                }
                const int a0 = 4 * kp;
                // hi*hi (4 indep), hi*lo (4), lo*hi (4): dep distance 4
                mma16816(sacc[a0 + 0], qh[kt], th[0][0], th[0][2]);
                mma16816(sacc[a0 + 1], qh[kt], th[0][1], th[0][3]);
                mma16816(sacc[a0 + 2], qh[kt], th[1][0], th[1][2]);
                mma16816(sacc[a0 + 3], qh[kt], th[1][1], th[1][3]);
                mma16816(sacc[a0 + 0], qh[kt], tl[0][0], tl[0][2]);
                mma16816(sacc[a0 + 1], qh[kt], tl[0][1], tl[0][3]);
                mma16816(sacc[a0 + 2], qh[kt], tl[1][0], tl[1][2]);
                mma16816(sacc[a0 + 3], qh[kt], tl[1][1], tl[1][3]);
                mma16816(sacc[a0 + 0], ql[kt], th[0][0], th[0][2]);
                mma16816(sacc[a0 + 1], ql[kt], th[0][1], th[0][3]);
                mma16816(sacc[a0 + 2], ql[kt], th[1][0], th[1][2]);
                mma16816(sacc[a0 + 3], ql[kt], th[1][1], th[1][3]);
            }
        }

        // ---- scale ----
#pragma unroll
        for (int j = 0; j < 8; j++)
#pragma unroll
            for (int e = 0; e < 4; e++) sacc[j][e] *= SCALE;

        // ---- causal mask on diagonal block ----
        if (kb == qb) {
            const int r0 = warp * 16 + tg;
#pragma unroll
            for (int j = 0; j < 8; j++) {
                const int c0 = j * 8 + tq * 2;
                if (c0     > r0)     sacc[j][0] = NEGV;
                if (c0 + 1 > r0)     sacc[j][1] = NEGV;
                if (c0     > r0 + 8) sacc[j][2] = NEGV;
                if (c0 + 1 > r0 + 8) sacc[j][3] = NEGV;
            }
        }

        // ---- online softmax (2 rows per thread) ----
#pragma unroll
        for (int rr = 0; rr < 2; rr++) {
            const int e0 = rr * 2;
            float mx = sacc[0][e0];
#pragma unroll
            for (int j = 0; j < 8; j++)
                mx = fmaxf(mx, fmaxf(sacc[j][e0], sacc[j][e0 + 1]));
            mx = fmaxf(mx, __shfl_xor_sync(0xffffffffu, mx, 1));
            mx = fmaxf(mx, __shfl_xor_sync(0xffffffffu, mx, 2));
            const float mn = fmaxf(mrow[rr], mx);
            const float corr = __expf(mrow[rr] - mn);
            float ps = 0.f;
#pragma unroll
            for (int j = 0; j < 8; j++) {
                const float p0 = __expf(sacc[j][e0] - mn);
                const float p1 = __expf(sacc[j][e0 + 1] - mn);
                sacc[j][e0] = p0; sacc[j][e0 + 1] = p1;
                ps += p0 + p1;
            }
            ps += __shfl_xor_sync(0xffffffffu, ps, 1);
            ps += __shfl_xor_sync(0xffffffffu, ps, 2);
            lrow[rr] = lrow[rr] * corr + ps;
            mrow[rr] = mn;
#pragma unroll
            for (int j = 0; j < 8; j++) {
                oacc[j][e0] *= corr; oacc[j][e0 + 1] *= corr;
            }
        }

        // ---- O += P V (V via ldsm.trans; dg pairs, term-major) ----
#pragma unroll
        for (int kk = 0; kk < 4; kk++) {
            uint32_t aPh[4], aPl[4];
            packsplit2(sacc[2 * kk][0],     sacc[2 * kk][1],     aPh[0], aPl[0]);
            packsplit2(sacc[2 * kk][2],     sacc[2 * kk][3],     aPh[1], aPl[1]);
            packsplit2(sacc[2 * kk + 1][0], sacc[2 * kk + 1][1], aPh[2], aPl[2]);
            packsplit2(sacc[2 * kk + 1][2], sacc[2 * kk + 1][3], aPh[3], aPl[3]);
#pragma unroll
            for (int dp = 0; dp < 2; dp++) {   // dg pair {2dp, 2dp+1}
                uint32_t vh[2][4], vl[2][4];
#pragma unroll
                for (int u = 0; u < 2; u++) {
                    const uint32_t va = stV + (uint32_t)(kk * 16) * VROWB + fragoff +
                                        (2 * dp + u) * 32;
                    ldsm4t(vh[u], va);
                    ldsm4t(vl[u], va + TILEB);
                }
                const int a0 = 4 * dp;
                mma16816(oacc[a0 + 0], aPh, vh[0][0], vh[0][1]);
                mma16816(oacc[a0 + 1], aPh, vh[0][2], vh[0][3]);
                mma16816(oacc[a0 + 2], aPh, vh[1][0], vh[1][1]);
                mma16816(oacc[a0 + 3], aPh, vh[1][2], vh[1][3]);
                mma16816(oacc[a0 + 0], aPh, vl[0][0], vl[0][1]);
                mma16816(oacc[a0 + 1], aPh, vl[0][2], vl[0][3]);
                mma16816(oacc[a0 + 2], aPh, vl[1][0], vl[1][1]);
                mma16816(oacc[a0 + 3], aPh, vl[1][2], vl[1][3]);
                mma16816(oacc[a0 + 0], aPl, vh[0][0], vh[0][1]);
                mma16816(oacc[a0 + 1], aPl, vh[0][2], vh[0][3]);
                mma16816(oacc[a0 + 2], aPl, vh[1][0], vh[1][1]);
                mma16816(oacc[a0 + 3], aPl, vh[1][2], vh[1][3]);
            }
        }
        __syncthreads();
    }

    // ---- epilogue ----
    const float inv0 = 1.f / lrow[0];
    const float inv1 = 1.f / lrow[1];
    const int grow0 = b * SEQ + qb * 64 + warp * 16 + tg;
    const int grow1 = grow0 + 8;
#pragma unroll
    for (int j = 0; j < 8; j++) {
        const int col = h * DHEAD + j * 8 + tq * 2;
        uint32_t hp, lp;
        packsplit2(oacc[j][0] * inv0, oacc[j][1] * inv0, hp, lp);
        *(uint32_t*)&ohi[(size_t)grow0 * INNER + col] = hp;
        *(uint32_t*)&olo[(size_t)grow0 * INNER + col] = lp;
        packsplit2(oacc[j][2] * inv1, oacc[j][3] * inv1, hp, lp);
        *(uint32_t*)&ohi[(size_t)grow1 * INNER + col] = hp;
        *(uint32_t*)&olo[(size_t)grow1 * INNER + col] = lp;
    }
}

// ---------------------------------------------------------------------------
extern "C" void kernel_launch(void* const* d_in, const int* in_sizes, int n_in,
                              void* d_out, int out_size)
{
    const float* x     = (const float*)d_in[0];
    const float* w_qkv = (const float*)d_in[1];
    const float* w_out = (const float*)d_in[2];
    const float* b_out = (const float*)d_in[3];
    float* out = (float*)d_out;

    __nv_bfloat16 *qh, *qlo, *xhi, *xlo, *wqh, *wql, *woh, *wol, *ahi, *alo;
    cudaGetSymbolAddress((void**)&qh,  g_qkvhi);
    cudaGetSymbolAddress((void**)&qlo, g_qkvlo);
    cudaGetSymbolAddress((void**)&xhi, g_xhi);
    cudaGetSymbolAddress((void**)&xlo, g_xlo);
    cudaGetSymbolAddress((void**)&wqh, g_wqkv_hi);
    cudaGetSymbolAddress((void**)&wql, g_wqkv_lo);
    cudaGetSymbolAddress((void**)&woh, g_wout_hi);
    cudaGetSymbolAddress((void**)&wol, g_wout_lo);
    cudaGetSymbolAddress((void**)&ahi, g_attnhi);
    cudaGetSymbolAddress((void**)&alo, g_attnlo);

    cudaFuncSetAttribute(gemm_mma,  cudaFuncAttributeMaxDynamicSharedMemorySize, 2 * BUFB);
    cudaFuncSetAttribute(flash_mma, cudaFuncAttributeMaxDynamicSharedMemorySize,
                         2 * TILEB + 2 * STAGEB);

    // 1) splits
    {
        int n4 = MTOT * DIM / 4;
        split_rows<<<(n4 + 255) / 256, 256>>>(x, xhi, xlo, n4);
        split_T<<<dim3(QKV3 / 32, DIM / 32), 256>>>(w_qkv, wqh, wql, DIM, QKV3);
        split_T<<<dim3(DIM / 32, INNER / 32), 256>>>(w_out, woh, wol, INNER, DIM);
    }
    // 2) QKV projection -> bf16 hi/lo
    gemm_mma<<<dim3(QKV3 / 128, MTOT / 128), 256, 2 * BUFB>>>(
        xhi, xlo, wqh, wql, nullptr, qh, qlo, QKV3, DIM, nullptr);
    // 3) attention
    flash_mma<<<dim3(BATCH * HEADS, SEQ / 64), 128, 2 * TILEB + 2 * STAGEB>>>(ahi, alo);
    // 4) output projection + bias (f32)
    gemm_mma<<<dim3(DIM / 128, MTOT / 128), 256, 2 * BUFB>>>(
        ahi, alo, woh, wol, out, nullptr, nullptr, DIM, INNER, b_out);
}

// round 9
// speedup vs baseline: 7.3930x; 1.0616x over previous
#include <cuda_runtime.h>
#include <cuda_bf16.h>
#include <cstdint>
#include <math.h>

#define BATCH 4
#define SEQ   2048
#define DIM   1024
#define HEADS 16
#define DHEAD 64
#define INNER 1024
#define QKV3  3072
#define SCALE 0.125f
#define NEGV  (-1e9f)
#define MTOT  (BATCH * SEQ)   // 8192

// ---------------------------------------------------------------------------
// Device scratch (allocation-free)
// ---------------------------------------------------------------------------
__device__ __nv_bfloat16  g_qkvhi[(size_t)MTOT * QKV3];      // 48 MB
__device__ __nv_bfloat16  g_qkvlo[(size_t)MTOT * QKV3];      // 48 MB
__device__ __nv_bfloat16  g_xhi[(size_t)MTOT * DIM];
__device__ __nv_bfloat16  g_xlo[(size_t)MTOT * DIM];
__device__ __nv_bfloat16  g_wqkv_hi[(size_t)QKV3 * DIM];     // [N][K]
__device__ __nv_bfloat16  g_wqkv_lo[(size_t)QKV3 * DIM];
__device__ __nv_bfloat16  g_wout_hi[(size_t)DIM * INNER];    // [N][K]
__device__ __nv_bfloat16  g_wout_lo[(size_t)DIM * INNER];
__device__ __nv_bfloat16  g_attnhi[(size_t)MTOT * INNER];
__device__ __nv_bfloat16  g_attnlo[(size_t)MTOT * INNER];

// ---------------------------------------------------------------------------
__device__ __forceinline__ uint32_t smem_to_u32(const void* p) {
    uint32_t a;
    asm("{ .reg .u64 t; cvta.to.shared.u64 t, %1; cvt.u32.u64 %0, t; }" : "=r"(a) : "l"(p));
    return a;
}
__device__ __forceinline__ void ldsm4(uint32_t (&r)[4], uint32_t addr) {
    asm volatile("ldmatrix.sync.aligned.m8n8.x4.shared.b16 {%0,%1,%2,%3}, [%4];"
        : "=r"(r[0]), "=r"(r[1]), "=r"(r[2]), "=r"(r[3]) : "r"(addr));
}
__device__ __forceinline__ void ldsm4t(uint32_t (&r)[4], uint32_t addr) {
    asm volatile("ldmatrix.sync.aligned.m8n8.x4.trans.shared.b16 {%0,%1,%2,%3}, [%4];"
        : "=r"(r[0]), "=r"(r[1]), "=r"(r[2]), "=r"(r[3]) : "r"(addr));
}
__device__ __forceinline__ void mma16816(float (&d)[4], const uint32_t (&a)[4],
                                         uint32_t b0, uint32_t b1) {
    asm volatile("mma.sync.aligned.m16n8k16.row.col.f32.bf16.bf16.f32 "
        "{%0,%1,%2,%3}, {%4,%5,%6,%7}, {%8,%9}, {%0,%1,%2,%3};"
        : "+f"(d[0]), "+f"(d[1]), "+f"(d[2]), "+f"(d[3])
        : "r"(a[0]), "r"(a[1]), "r"(a[2]), "r"(a[3]), "r"(b0), "r"(b1));
}
__device__ __forceinline__ void cpasync16(uint32_t dst, const void* src) {
    asm volatile("cp.async.cg.shared.global [%0], [%1], 16;" :: "r"(dst), "l"(src));
}
#define CP_COMMIT  asm volatile("cp.async.commit_group;" ::: "memory")
#define CP_WAIT1   asm volatile("cp.async.wait_group 1;" ::: "memory")
#define CP_WAIT0   asm volatile("cp.async.wait_group 0;" ::: "memory")

__device__ __forceinline__ void split2(float v, __nv_bfloat16& hi, __nv_bfloat16& lo) {
    hi = __float2bfloat16(v);
    lo = __float2bfloat16(v - __bfloat162float(hi));
}
__device__ __forceinline__ uint32_t packbf(__nv_bfloat16 a, __nv_bfloat16 b) {
    return (uint32_t)__bfloat16_as_ushort(a) | ((uint32_t)__bfloat16_as_ushort(b) << 16);
}
__device__ __forceinline__ void packsplit2(float a, float b, uint32_t& hi, uint32_t& lo) {
    __nv_bfloat16 ah, al, bh, bl;
    split2(a, ah, al); split2(b, bh, bl);
    hi = packbf(ah, bh); lo = packbf(al, bl);
}

// ---------------------------------------------------------------------------
// Conversion kernels
// ---------------------------------------------------------------------------
__global__ __launch_bounds__(256)
void split_rows(const float* __restrict__ in, __nv_bfloat16* __restrict__ hi,
                __nv_bfloat16* __restrict__ lo, int n4)
{
    int i = blockIdx.x * 256 + threadIdx.x;
    if (i >= n4) return;
    float4 v = ((const float4*)in)[i];
    __nv_bfloat16 h[4], l[4];
    split2(v.x, h[0], l[0]); split2(v.y, h[1], l[1]);
    split2(v.z, h[2], l[2]); split2(v.w, h[3], l[3]);
    uint2 hv, lv;
    hv.x = packbf(h[0], h[1]); hv.y = packbf(h[2], h[3]);
    lv.x = packbf(l[0], l[1]); lv.y = packbf(l[2], l[3]);
    ((uint2*)hi)[i] = hv;
    ((uint2*)lo)[i] = lv;
}

// in[K][N] -> out[N][K] (hi/lo)
__global__ __launch_bounds__(256)
void split_T(const float* __restrict__ in, __nv_bfloat16* __restrict__ hi,
             __nv_bfloat16* __restrict__ lo, int K, int N)
{
    __shared__ float t[32][33];
    const int k0 = blockIdx.y * 32, n0 = blockIdx.x * 32;
    const int tx = threadIdx.x & 31, ty = threadIdx.x >> 5;
#pragma unroll
    for (int i = 0; i < 32; i += 8)
        t[ty + i][tx] = in[(size_t)(k0 + ty + i) * N + n0 + tx];
    __syncthreads();
#pragma unroll
    for (int i = 0; i < 32; i += 8) {
        __nv_bfloat16 h, l;
        split2(t[tx][ty + i], h, l);
        size_t o = (size_t)(n0 + ty + i) * K + k0 + tx;
        hi[o] = h; lo[o] = l;
    }
}

// ---------------------------------------------------------------------------
// mma.sync bf16-split GEMM: C = A[M,K]*B[N,K]^T
// 128x64 CTA tile, 128 threads (4 warps, 2m x 2n, warp tile 64x32), BK=32,
// 2-stage cp.async, 3 CTAs/SM (desynchronized ldsm/mma phases across CTAs).
// smem/stage: Ah,Al 128x80 + Bh,Bl 64x80 = 30720 B; 2 stages = 61440 B
// ---------------------------------------------------------------------------
#define SROWB 80
#define OA_L  10240               // 128*80
#define OB_H  20480
#define OB_L  25600               // +64*80
#define STG   30720

__global__ __launch_bounds__(128, 3)
void gemm_mma(const __nv_bfloat16* __restrict__ Ahi, const __nv_bfloat16* __restrict__ Alo,
              const __nv_bfloat16* __restrict__ Bhi, const __nv_bfloat16* __restrict__ Blo,
              float* __restrict__ C, __nv_bfloat16* __restrict__ Chi,
              __nv_bfloat16* __restrict__ Clo,
              int Nout, int K, const float* __restrict__ bias)
{
    extern __shared__ char sm[];
    const uint32_t sb = smem_to_u32(sm);
    const int tid = threadIdx.x;
    const int wid = tid >> 5, lane = tid & 31;
    const int wm = wid >> 1, wn = wid & 1;
    const int brow = blockIdx.y * 128, bcol = blockIdx.x * 64;
    const int nch = K / 32;

    float acc[4][4][4];
#pragma unroll
    for (int mt = 0; mt < 4; mt++)
#pragma unroll
        for (int nt = 0; nt < 4; nt++)
#pragma unroll
            for (int i = 0; i < 4; i++) acc[mt][nt][i] = 0.f;

    // 1536 16B chunks per stage: Ah[0,512) Al[512,1024) Bh[1024,1280) Bl[1280,1536)
    auto issue = [&](int c) {
        const uint32_t base = sb + (uint32_t)(c & 1) * STG;
        const int koff = c * 32;
#pragma unroll
        for (int j = 0; j < 12; j++) {
            const int q = tid + j * 128;
            const int ch = q & 3;
            if (q < 1024) {
                const int r = (q & 511) >> 2;
                const uint32_t moff = (q < 512) ? 0u : (uint32_t)OA_L;
                const __nv_bfloat16* src = (q < 512) ? Ahi : Alo;
                cpasync16(base + moff + r * SROWB + ch * 16,
                          src + (size_t)(brow + r) * K + koff + ch * 8);
            } else {
                const int r = (q & 255) >> 2;
                const uint32_t moff = (q < 1280) ? (uint32_t)OB_H : (uint32_t)OB_L;
                const __nv_bfloat16* src = (q < 1280) ? Bhi : Blo;
                cpasync16(base + moff + r * SROWB + ch * 16,
                          src + (size_t)(bcol + r) * K + koff + ch * 8);
            }
        }
    };

    issue(0); CP_COMMIT;

    const uint32_t arow  = sb + (uint32_t)(wm * 64 + (lane & 15)) * SROWB + (lane >> 4) * 16;
    const uint32_t brow_s = sb + (uint32_t)(wn * 32 + (lane & 15)) * SROWB + (lane >> 4) * 16;

    for (int c = 0; c < nch; c++) {
        if (c + 1 < nch) { issue(c + 1); CP_COMMIT; CP_WAIT1; }
        else             { CP_WAIT0; }
        __syncthreads();
        const uint32_t boff = (uint32_t)(c & 1) * STG;
#pragma unroll
        for (int ks = 0; ks < 2; ks++) {
            const uint32_t kso = boff + ks * 32;
            uint32_t afh[4][4], afl[4][4];
#pragma unroll
            for (int mt = 0; mt < 4; mt++) {
                ldsm4(afh[mt], arow + mt * 16 * SROWB + kso);
                ldsm4(afl[mt], arow + OA_L + mt * 16 * SROWB + kso);
            }
            uint32_t bfh[4][2], bfl[4][2];
#pragma unroll
            for (int nb = 0; nb < 2; nb++) {
                uint32_t t[4];
                ldsm4(t, brow_s + OB_H + nb * 16 * SROWB + kso);
                bfh[nb * 2 + 0][0] = t[0]; bfh[nb * 2 + 0][1] = t[2];
                bfh[nb * 2 + 1][0] = t[1]; bfh[nb * 2 + 1][1] = t[3];
                ldsm4(t, brow_s + OB_L + nb * 16 * SROWB + kso);
                bfl[nb * 2 + 0][0] = t[0]; bfl[nb * 2 + 0][1] = t[2];
                bfl[nb * 2 + 1][0] = t[1]; bfl[nb * 2 + 1][1] = t[3];
            }
#pragma unroll
            for (int mt = 0; mt < 4; mt++)
#pragma unroll
                for (int nt = 0; nt < 4; nt++)
                    mma16816(acc[mt][nt], afh[mt], bfh[nt][0], bfh[nt][1]);
#pragma unroll
            for (int mt = 0; mt < 4; mt++)
#pragma unroll
                for (int nt = 0; nt < 4; nt++)
                    mma16816(acc[mt][nt], afh[mt], bfl[nt][0], bfl[nt][1]);
#pragma unroll
            for (int mt = 0; mt < 4; mt++)
#pragma unroll
                for (int nt = 0; nt < 4; nt++)
                    mma16816(acc[mt][nt], afl[mt], bfh[nt][0], bfh[nt][1]);
        }
        __syncthreads();
    }

    const int tg = lane >> 2, tq = lane & 3;
    if (Chi) {
#pragma unroll
        for (int mt = 0; mt < 4; mt++) {
            const int row = brow + wm * 64 + mt * 16 + tg;
#pragma unroll
            for (int nt = 0; nt < 4; nt++) {
                const int col = bcol + wn * 32 + nt * 8 + tq * 2;
                uint32_t hp, lp;
                packsplit2(acc[mt][nt][0], acc[mt][nt][1], hp, lp);
                *(uint32_t*)&Chi[(size_t)row * Nout + col] = hp;
                *(uint32_t*)&Clo[(size_t)row * Nout + col] = lp;
                packsplit2(acc[mt][nt][2], acc[mt][nt][3], hp, lp);
                *(uint32_t*)&Chi[(size_t)(row + 8) * Nout + col] = hp;
                *(uint32_t*)&Clo[(size_t)(row + 8) * Nout + col] = lp;
            }
        }
    } else {
#pragma unroll
        for (int mt = 0; mt < 4; mt++) {
            const int row = brow + wm * 64 + mt * 16 + tg;
#pragma unroll
            for (int nt = 0; nt < 4; nt++) {
                const int col = bcol + wn * 32 + nt * 8 + tq * 2;
                float b0 = 0.f, b1 = 0.f;
                if (bias) { b0 = bias[col]; b1 = bias[col + 1]; }
                *(float2*)&C[(size_t)row * Nout + col] =
                    make_float2(acc[mt][nt][0] + b0, acc[mt][nt][1] + b1);
                *(float2*)&C[(size_t)(row + 8) * Nout + col] =
                    make_float2(acc[mt][nt][2] + b0, acc[mt][nt][3] + b1);
            }
        }
    }
}

// ---------------------------------------------------------------------------
// mma.sync flash attention, causal, pre-split bf16 inputs, cp.async loaders.
// grid (B*HEADS, SEQ/64), 128 threads, 2 CTAs/SM. V via ldmatrix.trans.
// smem: Qhi,Qlo (2 x 9216) + 2 stages x (Khi,Klo,Vhi,Vlo) = 92160 B
// ---------------------------------------------------------------------------
#define VROWB 144
#define TILEB 9216                 // 64 * 144
#define STAGEB (4 * TILEB)         // 36864

__global__ __launch_bounds__(128, 2)
void flash_mma(__nv_bfloat16* __restrict__ ohi, __nv_bfloat16* __restrict__ olo)
{
    extern __shared__ char sm[];
    const uint32_t sb = smem_to_u32(sm);
    const uint32_t oQh = 0, oQl = TILEB, oStage = 2 * TILEB;

    const int bh = blockIdx.x;
    const int b = bh / HEADS, h = bh % HEADS;
    const int qb = blockIdx.y;
    const int tid = threadIdx.x;
    const int warp = tid >> 5, lane = tid & 31;
    const int tg = lane >> 2, tq = lane & 3;

    const size_t rowbase = (size_t)(b * SEQ) * QKV3;
    const __nv_bfloat16* Qh = g_qkvhi + rowbase + h * DHEAD;
    const __nv_bfloat16* Ql = g_qkvlo + rowbase + h * DHEAD;
    const __nv_bfloat16* Kh = Qh + INNER;
    const __nv_bfloat16* Kl = Ql + INNER;
    const __nv_bfloat16* Vh = Qh + 2 * INNER;
    const __nv_bfloat16* Vl = Ql + 2 * INNER;

    auto issue_kv = [&](int kb2, int s) {
        const uint32_t st = sb + oStage + (uint32_t)s * STAGEB;
        const __nv_bfloat16* srcs[4] = {
            Kh + (size_t)(kb2 * 64) * QKV3, Kl + (size_t)(kb2 * 64) * QKV3,
            Vh + (size_t)(kb2 * 64) * QKV3, Vl + (size_t)(kb2 * 64) * QKV3 };
#pragma unroll
        for (int i = 0; i < 4; i++)
#pragma unroll
            for (int j = 0; j < 4; j++) {
                const int idx = tid + j * 128;
                const int r = idx >> 3, ch = idx & 7;
                cpasync16(st + i * TILEB + r * VROWB + ch * 16,
                          srcs[i] + (size_t)r * QKV3 + ch * 8);
            }
    };

    issue_kv(0, 0); CP_COMMIT;

    // ---- Q tile: plain loads (once) ----
    for (int idx = tid; idx < 512; idx += 128) {
        const int r = idx >> 3, ch = idx & 7;
        const size_t src = (size_t)(qb * 64 + r) * QKV3 + ch * 8;
        *(uint4*)(sm + oQh + r * VROWB + ch * 16) = *(const uint4*)(Qh + src);
        *(uint4*)(sm + oQl + r * VROWB + ch * 16) = *(const uint4*)(Ql + src);
    }
    __syncthreads();

    // ---- Q fragments in regs ----
    uint32_t qh[4][4], ql[4][4];
    {
        const uint32_t qa = sb + (uint32_t)(warp * 16 + (lane & 15)) * VROWB + ((lane >> 4) << 4);
#pragma unroll
        for (int kt = 0; kt < 4; kt++) {
            ldsm4(qh[kt], qa + oQh + kt * 32);
            ldsm4(ql[kt], qa + oQl + kt * 32);
        }
    }

    float oacc[8][4];
#pragma unroll
    for (int j = 0; j < 8; j++)
#pragma unroll
        for (int e = 0; e < 4; e++) oacc[j][e] = 0.f;
    float mrow[2] = { -1e30f, -1e30f };
    float lrow[2] = { 0.f, 0.f };

    const uint32_t fragoff = (uint32_t)(lane & 15) * VROWB + ((lane >> 4) << 4);

    for (int kb = 0; kb <= qb; kb++) {
        const int s = kb & 1;
        if (kb < qb) { issue_kv(kb + 1, s ^ 1); CP_COMMIT; CP_WAIT1; }
        else         { CP_WAIT0; }
        __syncthreads();
        const uint32_t stK = sb + oStage + (uint32_t)s * STAGEB;
        const uint32_t stV = stK + 2 * TILEB;

        // ---- S = Q K^T ----
        float sacc[8][4];
#pragma unroll
        for (int j = 0; j < 8; j++)
#pragma unroll
            for (int e = 0; e < 4; e++) sacc[j][e] = 0.f;
#pragma unroll
        for (int kt = 0; kt < 4; kt++) {
#pragma unroll
            for (int kp = 0; kp < 2; kp++) {
                uint32_t th[2][4], tl[2][4];
#pragma unroll
                for (int u = 0; u < 2; u++) {
                    const uint32_t ka = stK + (uint32_t)((2 * kp + u) * 16) * VROWB +
                                        fragoff + kt * 32;
                    ldsm4(th[u], ka);
                    ldsm4(tl[u], ka + TILEB);
                }
                const int a0 = 4 * kp;
                mma16816(sacc[a0 + 0], qh[kt], th[0][0], th[0][2]);
                mma16816(sacc[a0 + 1], qh[kt], th[0][1], th[0][3]);
                mma16816(sacc[a0 + 2], qh[kt], th[1][0], th[1][2]);
                mma16816(sacc[a0 + 3], qh[kt], th[1][1], th[1][3]);
                mma16816(sacc[a0 + 0], qh[kt], tl[0][0], tl[0][2]);
                mma16816(sacc[a0 + 1], qh[kt], tl[0][1], tl[0][3]);
                mma16816(sacc[a0 + 2], qh[kt], tl[1][0], tl[1][2]);
                mma16816(sacc[a0 + 3], qh[kt], tl[1][1], tl[1][3]);
                mma16816(sacc[a0 + 0], ql[kt], th[0][0], th[0][2]);
                mma16816(sacc[a0 + 1], ql[kt], th[0][1], th[0][3]);
                mma16816(sacc[a0 + 2], ql[kt], th[1][0], th[1][2]);
                mma16816(sacc[a0 + 3], ql[kt], th[1][1], th[1][3]);
            }
        }

#pragma unroll
        for (int j = 0; j < 8; j++)
#pragma unroll
            for (int e = 0; e < 4; e++) sacc[j][e] *= SCALE;

        if (kb == qb) {
            const int r0 = warp * 16 + tg;
#pragma unroll
            for (int j = 0; j < 8; j++) {
                const int c0 = j * 8 + tq * 2;
                if (c0     > r0)     sacc[j][0] = NEGV;
                if (c0 + 1 > r0)     sacc[j][1] = NEGV;
                if (c0     > r0 + 8) sacc[j][2] = NEGV;
                if (c0 + 1 > r0 + 8) sacc[j][3] = NEGV;
            }
        }

#pragma unroll
        for (int rr = 0; rr < 2; rr++) {
            const int e0 = rr * 2;
            float mx = sacc[0][e0];
#pragma unroll
            for (int j = 0; j < 8; j++)
                mx = fmaxf(mx, fmaxf(sacc[j][e0], sacc[j][e0 + 1]));
            mx = fmaxf(mx, __shfl_xor_sync(0xffffffffu, mx, 1));
            mx = fmaxf(mx, __shfl_xor_sync(0xffffffffu, mx, 2));
            const float mn = fmaxf(mrow[rr], mx);
            const float corr = __expf(mrow[rr] - mn);
            float ps = 0.f;
#pragma unroll
            for (int j = 0; j < 8; j++) {
                const float p0 = __expf(sacc[j][e0] - mn);
                const float p1 = __expf(sacc[j][e0 + 1] - mn);
                sacc[j][e0] = p0; sacc[j][e0 + 1] = p1;
                ps += p0 + p1;
            }
            ps += __shfl_xor_sync(0xffffffffu, ps, 1);
            ps += __shfl_xor_sync(0xffffffffu, ps, 2);
            lrow[rr] = lrow[rr] * corr + ps;
            mrow[rr] = mn;
#pragma unroll
            for (int j = 0; j < 8; j++) {
                oacc[j][e0] *= corr; oacc[j][e0 + 1] *= corr;
            }
        }

        // ---- O += P V ----
#pragma unroll
        for (int kk = 0; kk < 4; kk++) {
            uint32_t aPh[4], aPl[4];
            packsplit2(sacc[2 * kk][0],     sacc[2 * kk][1],     aPh[0], aPl[0]);
            packsplit2(sacc[2 * kk][2],     sacc[2 * kk][3],     aPh[1], aPl[1]);
            packsplit2(sacc[2 * kk + 1][0], sacc[2 * kk + 1][1], aPh[2], aPl[2]);
            packsplit2(sacc[2 * kk + 1][2], sacc[2 * kk + 1][3], aPh[3], aPl[3]);
#pragma unroll
            for (int dp = 0; dp < 2; dp++) {
                uint32_t vh[2][4], vl[2][4];
#pragma unroll
                for (int u = 0; u < 2; u++) {
                    const uint32_t va = stV + (uint32_t)(kk * 16) * VROWB + fragoff +
                                        (2 * dp + u) * 32;
                    ldsm4t(vh[u], va);
                    ldsm4t(vl[u], va + TILEB);
                }
                const int a0 = 4 * dp;
                mma16816(oacc[a0 + 0], aPh, vh[0][0], vh[0][1]);
                mma16816(oacc[a0 + 1], aPh, vh[0][2], vh[0][3]);
                mma16816(oacc[a0 + 2], aPh, vh[1][0], vh[1][1]);
                mma16816(oacc[a0 + 3], aPh, vh[1][2], vh[1][3]);
                mma16816(oacc[a0 + 0], aPh, vl[0][0], vl[0][1]);
                mma16816(oacc[a0 + 1], aPh, vl[0][2], vl[0][3]);
                mma16816(oacc[a0 + 2], aPh, vl[1][0], vl[1][1]);
                mma16816(oacc[a0 + 3], aPh, vl[1][2], vl[1][3]);
                mma16816(oacc[a0 + 0], aPl, vh[0][0], vh[0][1]);
                mma16816(oacc[a0 + 1], aPl, vh[0][2], vh[0][3]);
                mma16816(oacc[a0 + 2], aPl, vh[1][0], vh[1][1]);
                mma16816(oacc[a0 + 3], aPl, vh[1][2], vh[1][3]);
            }
        }
        __syncthreads();
    }

    // ---- epilogue ----
    const float inv0 = 1.f / lrow[0];
    const float inv1 = 1.f / lrow[1];
    const int grow0 = b * SEQ + qb * 64 + warp * 16 + tg;
    const int grow1 = grow0 + 8;
#pragma unroll
    for (int j = 0; j < 8; j++) {
        const int col = h * DHEAD + j * 8 + tq * 2;
        uint32_t hp, lp;
        packsplit2(oacc[j][0] * inv0, oacc[j][1] * inv0, hp, lp);
        *(uint32_t*)&ohi[(size_t)grow0 * INNER + col] = hp;
        *(uint32_t*)&olo[(size_t)grow0 * INNER + col] = lp;
        packsplit2(oacc[j][2] * inv1, oacc[j][3] * inv1, hp, lp);
        *(uint32_t*)&ohi[(size_t)grow1 * INNER + col] = hp;
        *(uint32_t*)&olo[(size_t)grow1 * INNER + col] = lp;
    }
}

// ---------------------------------------------------------------------------
extern "C" void kernel_launch(void* const* d_in, const int* in_sizes, int n_in,
                              void* d_out, int out_size)
{
    const float* x     = (const float*)d_in[0];
    const float* w_qkv = (const float*)d_in[1];
    const float* w_out = (const float*)d_in[2];
    const float* b_out = (const float*)d_in[3];
    float* out = (float*)d_out;

    __nv_bfloat16 *qh, *qlo, *xhi, *xlo, *wqh, *wql, *woh, *wol, *ahi, *alo;
    cudaGetSymbolAddress((void**)&qh,  g_qkvhi);
    cudaGetSymbolAddress((void**)&qlo, g_qkvlo);
    cudaGetSymbolAddress((void**)&xhi, g_xhi);
    cudaGetSymbolAddress((void**)&xlo, g_xlo);
    cudaGetSymbolAddress((void**)&wqh, g_wqkv_hi);
    cudaGetSymbolAddress((void**)&wql, g_wqkv_lo);
    cudaGetSymbolAddress((void**)&woh, g_wout_hi);
    cudaGetSymbolAddress((void**)&wol, g_wout_lo);
    cudaGetSymbolAddress((void**)&ahi, g_attnhi);
    cudaGetSymbolAddress((void**)&alo, g_attnlo);

    cudaFuncSetAttribute(gemm_mma,  cudaFuncAttributeMaxDynamicSharedMemorySize, 2 * STG);
    cudaFuncSetAttribute(flash_mma, cudaFuncAttributeMaxDynamicSharedMemorySize,
                         2 * TILEB + 2 * STAGEB);

    // 1) splits
    {
        int n4 = MTOT * DIM / 4;
        split_rows<<<(n4 + 255) / 256, 256>>>(x, xhi, xlo, n4);
        split_T<<<dim3(QKV3 / 32, DIM / 32), 256>>>(w_qkv, wqh, wql, DIM, QKV3);
        split_T<<<dim3(DIM / 32, INNER / 32), 256>>>(w_out, woh, wol, INNER, DIM);
    }
    // 2) QKV projection -> bf16 hi/lo
    gemm_mma<<<dim3(QKV3 / 64, MTOT / 128), 128, 2 * STG>>>(
        xhi, xlo, wqh, wql, nullptr, qh, qlo, QKV3, DIM, nullptr);
    // 3) attention
    flash_mma<<<dim3(BATCH * HEADS, SEQ / 64), 128, 2 * TILEB + 2 * STAGEB>>>(ahi, alo);
    // 4) output projection + bias (f32)
    gemm_mma<<<dim3(DIM / 64, MTOT / 128), 128, 2 * STG>>>(
        ahi, alo, woh, wol, out, nullptr, nullptr, DIM, INNER, b_out);
}